// round 11
// baseline (speedup 1.0000x reference)
#include <cuda_runtime.h>
#include <cuda_bf16.h>
#include <cstdint>
#include <math.h>

#define Bv 8
#define Cv 128
#define Hv 96
#define Wv 96
#define HWv (Hv * Wv)        // 9216
#define Kv 9
#define KD (Cv * Kv)         // 1152
#define OCOFF 27
#define EPSv 1e-5f

// ---------------- scratch (device globals; no runtime allocation) ----------------
__device__ float  g_xT[(size_t)Bv * HWv * Cv];   // hw-major input (layer 1)
__device__ float  g_o1T[(size_t)Bv * HWv * Cv];  // hw-major layer-1 output
__device__ float  g_wt[Cv * KD];                 // transposed dcn weight, tf32
__device__ float  g_wt2[32 * KD];                // transposed offset weight (27->32 pad), tf32
__device__ int4   g_pidx[Bv * Kv * HWv];
__device__ float4 g_pw[Bv * Kv * HWv];
__device__ float  g_mx[Bv * Cv];
__device__ float  g_av[Bv * Cv];
__device__ float  g_ch[Bv * Cv];

__device__ __forceinline__ float to_tf32(float v) {
    float r;
    asm("cvt.rna.tf32.f32 %0, %1;" : "=f"(r) : "f"(v));
    return r;
}

__device__ __forceinline__ void cpa16(float* sdst, const float* gsrc) {
    unsigned int s = (unsigned int)__cvta_generic_to_shared(sdst);
    asm volatile("cp.async.cg.shared.global [%0], [%1], 16;\n" :: "r"(s), "l"(gsrc));
}

__device__ __forceinline__ void mma_tf32(float* d, const float* a, const float* bfr) {
    asm volatile(
        "mma.sync.aligned.m16n8k8.row.col.f32.tf32.tf32.f32 "
        "{%0,%1,%2,%3}, {%4,%5,%6,%7}, {%8,%9}, {%0,%1,%2,%3};\n"
        : "+f"(d[0]), "+f"(d[1]), "+f"(d[2]), "+f"(d[3])
        : "r"(__float_as_uint(a[0])), "r"(__float_as_uint(a[1])),
          "r"(__float_as_uint(a[2])), "r"(__float_as_uint(a[3])),
          "r"(__float_as_uint(bfr[0])), "r"(__float_as_uint(bfr[1])));
}

// ---------------- transpose x: (C, HW) -> (HW, C) per batch ----------------
__global__ void transpose_kernel(const float* __restrict__ src, float* __restrict__ dst) {
    __shared__ float tile[32][33];
    const int b = blockIdx.z;
    const int hw0 = blockIdx.x * 32;
    const int c0  = blockIdx.y * 32;
    const int tx = threadIdx.x, ty = threadIdx.y;   // (32, 8)
    const float* s = src + (size_t)b * Cv * HWv;
    float* d = dst + (size_t)b * HWv * Cv;
#pragma unroll
    for (int i = 0; i < 4; i++)
        tile[ty + i * 8][tx] = s[(size_t)(c0 + ty + i * 8) * HWv + hw0 + tx];
    __syncthreads();
#pragma unroll
    for (int i = 0; i < 4; i++)
        d[(size_t)(hw0 + ty + i * 8) * Cv + c0 + tx] = tile[tx][ty + i * 8];
}

// ---------------- weight transposes (tf32-rounded) ----------------
__global__ void wtrans_kernel(const float* __restrict__ w, float* __restrict__ wt) {
    int t = blockIdx.x * blockDim.x + threadIdx.x;
    if (t >= Cv * KD) return;
    int o = t / KD, r = t % KD, k = r / Cv, i = r % Cv;
    wt[t] = to_tf32(w[((size_t)o * Cv + i) * Kv + k]);
}

__global__ void wtrans_off_kernel(const float* __restrict__ w, float* __restrict__ wt2) {
    int t = blockIdx.x * blockDim.x + threadIdx.x;
    if (t >= 32 * KD) return;
    int o = t / KD, r = t % KD, k = r / Cv, i = r % Cv;
    wt2[t] = (o < OCOFF) ? to_tf32(w[((size_t)o * Cv + i) * Kv + k]) : 0.f;
}

// ================= tile constants =================
#define TBN 128
#define TBK 32
#define NT (KD / TBK)        // 36
#define AS_STRIDE 36
#define BS_STRIDE 36          // n-major B: Bs[n][k]
#define STAGE_A (128 * AS_STRIDE)      // 4608
#define STAGE_B (128 * BS_STRIDE)      // 4608
#define STAGE_F (STAGE_A + STAGE_B)    // 9216
#define GEMM_SMEM (2 * STAGE_F * 4)    // 73728 B  (18432 floats; >= 128*132 staging)
#define STG_STRIDE 132                 // 528 B: 16B-aligned, conflict-free copy rows

#define OSTAGE_A (32 * AS_STRIDE)          // 1152
#define OSTAGE_F (OSTAGE_A + STAGE_B)      // 5760
#define OGEMM_SMEM (2 * OSTAGE_F * 4)      // 46080 B
#define SOM_STRIDE 132

// ---------------- offset GEMM (tf32, reads xT) + fused prep ----------------
__global__ void __launch_bounds__(256)
off_gemm_prep_kernel(const float* __restrict__ wt2,   // (32, KD) tf32
                     const float* __restrict__ xT,    // (B, HW, C)
                     const float* __restrict__ off_b, // (27)
                     int4* __restrict__ pidx,
                     float4* __restrict__ pw) {
    extern __shared__ float smem[];
    const int b   = blockIdx.y;
    const int n0  = blockIdx.x * TBN;
    const int tid = threadIdx.x;
    const int warp = tid >> 5, lane = tid & 31;
    const int gid = lane >> 2, tig = lane & 3;
    const int q  = lane >> 3, cl = lane & 7;
    const int wm = (warp & 1) * 16;
    const int wn = (warp >> 1) * 32;
    const float* xb = xT + (size_t)b * HWv * Cv;

    float acc[4][4];
#pragma unroll
    for (int j = 0; j < 4; j++)
#pragma unroll
        for (int c = 0; c < 4; c++) acc[j][c] = 0.f;

    auto issueA = [&](int kt) {
        float* As = smem + (kt & 1) * OSTAGE_F;
        const int k0 = kt * TBK;
        int m = tid >> 3, kkv = (tid & 7) << 2;
        cpa16(As + m * AS_STRIDE + kkv, wt2 + (size_t)m * KD + k0 + kkv);
        asm volatile("cp.async.commit_group;\n" ::);
    };

    auto buildB = [&](int kt) {
        const int kp = kt >> 2, cg = kt & 3;
        const int dyk = kp / 3 - 1, dxk = kp % 3 - 1;
        float* Bs = smem + (kt & 1) * OSTAGE_F + OSTAGE_A;
#pragma unroll
        for (int r = 0; r < 4; r++) {
            int hwl = warp * 16 + r * 4 + q;
            int hw = n0 + hwl;
            int h = hw / Wv, w = hw % Wv;
            bool valid = ((unsigned)(h + dyk) < Hv) && ((unsigned)(w + dxk) < Wv);
            float4 v = make_float4(0.f, 0.f, 0.f, 0.f);
            if (valid) {
                int idx = hw + dyk * Wv + dxk;
                v = *(const float4*)(xb + (size_t)idx * Cv + cg * 32 + cl * 4);
            }
            v.x = to_tf32(v.x); v.y = to_tf32(v.y);
            v.z = to_tf32(v.z); v.w = to_tf32(v.w);
            *(float4*)(Bs + hwl * BS_STRIDE + cl * 4) = v;
        }
    };

    issueA(0);
    buildB(0);
    __syncthreads();
    for (int kt = 0; kt < NT; kt++) {
        if (kt + 1 < NT) {
            issueA(kt + 1);
            asm volatile("cp.async.wait_group 1;\n" ::);   // A(kt) landed
            buildB(kt + 1);                                // other buffer; overlaps mma below
        } else {
            asm volatile("cp.async.wait_group 0;\n" ::);
        }
        const float* As = smem + (kt & 1) * OSTAGE_F;
        const float* Bs = As + OSTAGE_A;
#pragma unroll
        for (int s = 0; s < 4; s++) {
            const int ks = s * 8;
            float afr[4];
            int m = wm + gid;
            afr[0] = As[m * AS_STRIDE + ks + tig];
            afr[1] = As[(m + 8) * AS_STRIDE + ks + tig];
            afr[2] = As[m * AS_STRIDE + ks + tig + 4];
            afr[3] = As[(m + 8) * AS_STRIDE + ks + tig + 4];
            float bfr[4][2];
#pragma unroll
            for (int nj = 0; nj < 4; nj++) {
                int n = wn + nj * 8 + gid;
                bfr[nj][0] = Bs[n * BS_STRIDE + ks + tig];
                bfr[nj][1] = Bs[n * BS_STRIDE + ks + tig + 4];
            }
#pragma unroll
            for (int nj = 0; nj < 4; nj++)
                mma_tf32(acc[nj], afr, bfr[nj]);
        }
        __syncthreads();
    }

    // ---- stage om tile (32 x 128) into smem with bias ----
    float* som = smem;
    {
        int o0 = wm + gid, o1r = o0 + 8;
        float bb0 = (o0 < OCOFF) ? off_b[o0] : 0.f;
        float bb1 = (o1r < OCOFF) ? off_b[o1r] : 0.f;
#pragma unroll
        for (int nj = 0; nj < 4; nj++) {
            int ncol = wn + nj * 8 + 2 * tig;
            som[o0 * SOM_STRIDE + ncol]      = acc[nj][0] + bb0;
            som[o0 * SOM_STRIDE + ncol + 1]  = acc[nj][1] + bb0;
            som[o1r * SOM_STRIDE + ncol]     = acc[nj][2] + bb1;
            som[o1r * SOM_STRIDE + ncol + 1] = acc[nj][3] + bb1;
        }
    }
    __syncthreads();

    // ---- prep: pidx / pw for all (k, col) of this tile ----
    for (int t = tid; t < Kv * TBN; t += 256) {
        int k = t / TBN, col = t % TBN;
        int phw = n0 + col;
        int ph = phw / Wv, pwd = phw % Wv;
        float dy = som[(2 * k) * SOM_STRIDE + col];
        float dx = som[(2 * k + 1) * SOM_STRIDE + col];
        float msk = 1.f / (1.f + expf(-som[(18 + k) * SOM_STRIDE + col]));

        float py = (float)ph - 1.f + (float)(k / 3) + dy;
        float px = (float)pwd - 1.f + (float)(k % 3) + dx;
        float y0f = floorf(py), x0f = floorf(px);
        float wy1 = py - y0f, wx1 = px - x0f;
        int y0 = (int)y0f, x0 = (int)x0f;
        int y1 = y0 + 1, x1 = x0 + 1;

        float w00 = (1.f - wy1) * (1.f - wx1) * msk;
        float w01 = (1.f - wy1) * wx1 * msk;
        float w10 = wy1 * (1.f - wx1) * msk;
        float w11 = wy1 * wx1 * msk;

        bool vy0 = (y0 >= 0 && y0 < Hv), vy1 = (y1 >= 0 && y1 < Hv);
        bool vx0 = (x0 >= 0 && x0 < Wv), vx1 = (x1 >= 0 && x1 < Wv);
        if (!(vy0 && vx0)) w00 = 0.f;
        if (!(vy0 && vx1)) w01 = 0.f;
        if (!(vy1 && vx0)) w10 = 0.f;
        if (!(vy1 && vx1)) w11 = 0.f;

        int iy0 = min(max(y0, 0), Hv - 1), iy1 = min(max(y1, 0), Hv - 1);
        int ix0 = min(max(x0, 0), Wv - 1), ix1 = min(max(x1, 0), Wv - 1);

        size_t gi = ((size_t)b * Kv + k) * HWv + phw;
        pidx[gi] = make_int4(iy0 * Wv + ix0, iy0 * Wv + ix1,
                             iy1 * Wv + ix0, iy1 * Wv + ix1);
        pw[gi]   = make_float4(w00, w01, w10, w11);
    }
}

// ---------------- fused gather(xT) + tf32 GEMM + bias/BN/ReLU ----------------
__global__ void __launch_bounds__(256, 2)
fused_dcn_gemm_kernel(const float* __restrict__ wt,     // (C, KD) tf32
                      const float* __restrict__ xT,     // (B, HW, C)
                      const int4*  __restrict__ pidx,
                      const float4* __restrict__ pw,
                      const float* __restrict__ bias,
                      const float* __restrict__ bn_g,
                      const float* __restrict__ bn_b,
                      const float* __restrict__ bn_m,
                      const float* __restrict__ bn_v,
                      float* __restrict__ out,          // (B,C,HW) or (B,HW,C)
                      int transposed) {
    extern __shared__ float smem[];
    const int b   = blockIdx.y;
    const int n0  = blockIdx.x * TBN;
    const int tid = threadIdx.x;
    const int warp = tid >> 5, lane = tid & 31;
    const int gid = lane >> 2, tig = lane & 3;
    const int q  = lane >> 3, cl = lane & 7;
    const int wm = (warp & 1) * 64;
    const int wn = (warp >> 1) * 32;
    const float* xb = xT + (size_t)b * HWv * Cv;

    float acc[4][4][4];
#pragma unroll
    for (int i = 0; i < 4; i++)
#pragma unroll
        for (int j = 0; j < 4; j++)
#pragma unroll
            for (int c = 0; c < 4; c++) acc[i][j][c] = 0.f;

    auto issueA = [&](int kt) {
        float* As = smem + (kt & 1) * STAGE_F;
        const int k0 = kt * TBK;
#pragma unroll
        for (int r = 0; r < 4; r++) {
            int e = tid + r * 256;
            int m = e >> 3, kkv = (e & 7) << 2;
            cpa16(As + m * AS_STRIDE + kkv, wt + (size_t)m * KD + k0 + kkv);
        }
        asm volatile("cp.async.commit_group;\n" ::);
    };

    auto buildB = [&](int kt) {
        const int kp = kt >> 2, cg = kt & 3;
        float* Bs = smem + (kt & 1) * STAGE_F + STAGE_A;
#pragma unroll
        for (int r = 0; r < 4; r++) {
            int hwl = warp * 16 + r * 4 + q;
            size_t pbase = ((size_t)b * Kv + kp) * HWv + n0 + hwl;
            int4   id4 = __ldg(pidx + pbase);
            float4 w4  = __ldg(pw + pbase);
            const float* base = xb + cg * 32 + cl * 4;
            float4 c00 = *(const float4*)(base + (size_t)id4.x * Cv);
            float4 c01 = *(const float4*)(base + (size_t)id4.y * Cv);
            float4 c10 = *(const float4*)(base + (size_t)id4.z * Cv);
            float4 c11 = *(const float4*)(base + (size_t)id4.w * Cv);
            float4 v;
            v.x = to_tf32(w4.x * c00.x + w4.y * c01.x + w4.z * c10.x + w4.w * c11.x);
            v.y = to_tf32(w4.x * c00.y + w4.y * c01.y + w4.z * c10.y + w4.w * c11.y);
            v.z = to_tf32(w4.x * c00.z + w4.y * c01.z + w4.z * c10.z + w4.w * c11.z);
            v.w = to_tf32(w4.x * c00.w + w4.y * c01.w + w4.z * c10.w + w4.w * c11.w);
            *(float4*)(Bs + hwl * BS_STRIDE + cl * 4) = v;
        }
    };

    issueA(0);
    buildB(0);
    __syncthreads();
    for (int kt = 0; kt < NT; kt++) {
        if (kt + 1 < NT) {
            issueA(kt + 1);
            asm volatile("cp.async.wait_group 1;\n" ::);   // A(kt) landed
            buildB(kt + 1);                                // other buffer; overlaps mma across warps
        } else {
            asm volatile("cp.async.wait_group 0;\n" ::);
        }
        const float* As = smem + (kt & 1) * STAGE_F;
        const float* Bs = As + STAGE_A;
#pragma unroll
        for (int s = 0; s < 4; s++) {
            const int ks = s * 8;
            float afr[4][4];
#pragma unroll
            for (int mi = 0; mi < 4; mi++) {
                int m = wm + mi * 16 + gid;
                afr[mi][0] = As[m * AS_STRIDE + ks + tig];
                afr[mi][1] = As[(m + 8) * AS_STRIDE + ks + tig];
                afr[mi][2] = As[m * AS_STRIDE + ks + tig + 4];
                afr[mi][3] = As[(m + 8) * AS_STRIDE + ks + tig + 4];
            }
            float bfr[4][2];
#pragma unroll
            for (int nj = 0; nj < 4; nj++) {
                int n = wn + nj * 8 + gid;
                bfr[nj][0] = Bs[n * BS_STRIDE + ks + tig];
                bfr[nj][1] = Bs[n * BS_STRIDE + ks + tig + 4];
            }
#pragma unroll
            for (int mi = 0; mi < 4; mi++)
#pragma unroll
                for (int nj = 0; nj < 4; nj++)
                    mma_tf32(acc[mi][nj], afr[mi], bfr[nj]);
        }
        __syncthreads();
    }

    // ---- epilogue: bias + BN + ReLU, staged through smem for coalesced stores ----
    // (all pipeline reads finished at the final __syncthreads above; reuse smem)
    float* stg = smem;
#pragma unroll
    for (int mi = 0; mi < 4; mi++) {
        int o0 = wm + mi * 16 + gid;
        int o1r = o0 + 8;
        float sc0 = bn_g[o0]  * rsqrtf(bn_v[o0]  + EPSv);
        float sc1 = bn_g[o1r] * rsqrtf(bn_v[o1r] + EPSv);
        float bb0 = bias[o0] - bn_m[o0], bb1 = bias[o1r] - bn_m[o1r];
        float bt0 = bn_b[o0], bt1 = bn_b[o1r];
#pragma unroll
        for (int nj = 0; nj < 4; nj++) {
            int nl = wn + nj * 8 + 2 * tig;    // tile-local column
            float v00 = fmaxf((acc[mi][nj][0] + bb0) * sc0 + bt0, 0.f);
            float v01 = fmaxf((acc[mi][nj][1] + bb0) * sc0 + bt0, 0.f);
            float v10 = fmaxf((acc[mi][nj][2] + bb1) * sc1 + bt1, 0.f);
            float v11 = fmaxf((acc[mi][nj][3] + bb1) * sc1 + bt1, 0.f);
            if (transposed) {
                // stage sm[ncol][o]: banks (8*tig+gid) distinct -> conflict-free
                stg[nl * STG_STRIDE + o0]        = v00;
                stg[(nl + 1) * STG_STRIDE + o0]  = v01;
                stg[nl * STG_STRIDE + o1r]       = v10;
                stg[(nl + 1) * STG_STRIDE + o1r] = v11;
            } else {
                // stage sm[o][ncol]: <=2-way STS conflicts, copy stays aligned
                stg[o0 * STG_STRIDE + nl]       = v00;
                stg[o0 * STG_STRIDE + nl + 1]   = v01;
                stg[o1r * STG_STRIDE + nl]      = v10;
                stg[o1r * STG_STRIDE + nl + 1]  = v11;
            }
        }
    }
    __syncthreads();

    if (transposed) {
        float* ob = out + (size_t)b * HWv * Cv + (size_t)n0 * Cv;
#pragma unroll
        for (int it = 0; it < 16; it++) {
            int idx = tid + it * 256;          // 0..4095
            int row = idx >> 5;                // ncol 0..127
            int c4  = (idx & 31) << 2;         // o 0..124
            float4 v = *(const float4*)(stg + row * STG_STRIDE + c4);
            *(float4*)(ob + (size_t)row * Cv + c4) = v;
        }
    } else {
#pragma unroll
        for (int it = 0; it < 16; it++) {
            int idx = tid + it * 256;
            int row = idx >> 5;                // o 0..127
            int c4  = (idx & 31) << 2;         // ncol 0..124
            float4 v = *(const float4*)(stg + row * STG_STRIDE + c4);
            *(float4*)(out + ((size_t)b * Cv + row) * HWv + n0 + c4) = v;
        }
    }
}

// ---------------- global max/mean pool per (b,c) ----------------
__global__ void pool_kernel(const float* __restrict__ x,
                            float* __restrict__ mx, float* __restrict__ av) {
    int bc = blockIdx.x;
    const float* p = x + (size_t)bc * HWv;
    float vmax = -3.4e38f, vsum = 0.f;
    for (int i = threadIdx.x; i < HWv; i += 256) {
        float t = p[i];
        vmax = fmaxf(vmax, t);
        vsum += t;
    }
    __shared__ float sm[256], ss[256];
    sm[threadIdx.x] = vmax; ss[threadIdx.x] = vsum;
    __syncthreads();
    for (int s = 128; s > 0; s >>= 1) {
        if (threadIdx.x < s) {
            sm[threadIdx.x] = fmaxf(sm[threadIdx.x], sm[threadIdx.x + s]);
            ss[threadIdx.x] += ss[threadIdx.x + s];
        }
        __syncthreads();
    }
    if (threadIdx.x == 0) { mx[bc] = sm[0]; av[bc] = ss[0] * (1.f / HWv); }
}

// ---------------- channel-attention MLP ----------------
__global__ void cam_kernel(const float* __restrict__ mx, const float* __restrict__ av,
                           const float* __restrict__ w1,   // (32,128)
                           const float* __restrict__ w2,   // (128,32)
                           float* __restrict__ ch) {
    int b = blockIdx.x;
    int tid = threadIdx.x;
    __shared__ float smx[128], sav[128], sh[32];
    smx[tid] = mx[b * 128 + tid];
    sav[tid] = av[b * 128 + tid];
    __syncthreads();
    if (tid < 32) {
        float a = 0.f, c = 0.f;
        for (int i = 0; i < 128; i++) {
            float wv = w1[tid * 128 + i];
            a = fmaf(smx[i], wv, a);
            c = fmaf(sav[i], wv, c);
        }
        sh[tid] = fmaxf(a, 0.f) + fmaxf(c, 0.f);
    }
    __syncthreads();
    float o = 0.f;
#pragma unroll
    for (int j = 0; j < 32; j++) o = fmaf(sh[j], w2[tid * 32 + j], o);
    ch[b * 128 + tid] = 1.f / (1.f + expf(-o));
}

// ---------------- in-place channel scale ----------------
__global__ void scale_kernel(float* __restrict__ out, const float* __restrict__ ch) {
    size_t t = (size_t)blockIdx.x * blockDim.x + threadIdx.x;
    if (t >= (size_t)Bv * Cv * HWv) return;
    out[t] *= ch[t / HWv];
}

// ---------------- launch ----------------
extern "C" void kernel_launch(void* const* d_in, const int* in_sizes, int n_in,
                              void* d_out, int out_size) {
    const float* x      = (const float*)d_in[0];
    const float* off_w1 = (const float*)d_in[1];
    const float* off_b1 = (const float*)d_in[2];
    const float* dcn_w1 = (const float*)d_in[3];
    const float* dcn_b1 = (const float*)d_in[4];
    const float* bn_g1  = (const float*)d_in[5];
    const float* bn_b1  = (const float*)d_in[6];
    const float* bn_m1  = (const float*)d_in[7];
    const float* bn_v1  = (const float*)d_in[8];
    const float* off_w2 = (const float*)d_in[9];
    const float* off_b2 = (const float*)d_in[10];
    const float* dcn_w2 = (const float*)d_in[11];
    const float* dcn_b2 = (const float*)d_in[12];
    const float* bn_g2  = (const float*)d_in[13];
    const float* bn_b2  = (const float*)d_in[14];
    const float* bn_m2  = (const float*)d_in[15];
    const float* bn_v2  = (const float*)d_in[16];
    const float* cam_w1 = (const float*)d_in[17];
    const float* cam_w2 = (const float*)d_in[18];
    float* out = (float*)d_out;

    float *xT, *o1T, *wt, *wt2, *mxp, *avp, *chp;
    int4 *pidx; float4 *pw;
    cudaGetSymbolAddress((void**)&xT,   g_xT);
    cudaGetSymbolAddress((void**)&o1T,  g_o1T);
    cudaGetSymbolAddress((void**)&wt,   g_wt);
    cudaGetSymbolAddress((void**)&wt2,  g_wt2);
    cudaGetSymbolAddress((void**)&pidx, g_pidx);
    cudaGetSymbolAddress((void**)&pw,   g_pw);
    cudaGetSymbolAddress((void**)&mxp,  g_mx);
    cudaGetSymbolAddress((void**)&avp,  g_av);
    cudaGetSymbolAddress((void**)&chp,  g_ch);

    cudaFuncSetAttribute(fused_dcn_gemm_kernel,
                         cudaFuncAttributeMaxDynamicSharedMemorySize, GEMM_SMEM);
    cudaFuncSetAttribute(off_gemm_prep_kernel,
                         cudaFuncAttributeMaxDynamicSharedMemorySize, OGEMM_SMEM);

    int  wtGrid  = (Cv * KD + 255) / 256;
    int  wt2Grid = (32 * KD + 255) / 256;
    dim3 trGrid(HWv / 32, Cv / 32, Bv);
    dim3 trBlk(32, 8);
    dim3 gemmGrid(HWv / TBN, Bv);
    int  scaleGrid = (Bv * Cv * HWv + 255) / 256;

    // layer 1 (writes o1T hw-major directly)
    transpose_kernel<<<trGrid, trBlk>>>(x, xT);
    wtrans_off_kernel<<<wt2Grid, 256>>>(off_w1, wt2);
    wtrans_kernel<<<wtGrid, 256>>>(dcn_w1, wt);
    off_gemm_prep_kernel<<<gemmGrid, 256, OGEMM_SMEM>>>(wt2, xT, off_b1, pidx, pw);
    fused_dcn_gemm_kernel<<<gemmGrid, 256, GEMM_SMEM>>>(wt, xT, pidx, pw,
        dcn_b1, bn_g1, bn_b1, bn_m1, bn_v1, o1T, 1);

    // layer 2 (writes channel-major final)
    wtrans_off_kernel<<<wt2Grid, 256>>>(off_w2, wt2);
    wtrans_kernel<<<wtGrid, 256>>>(dcn_w2, wt);
    off_gemm_prep_kernel<<<gemmGrid, 256, OGEMM_SMEM>>>(wt2, o1T, off_b2, pidx, pw);
    fused_dcn_gemm_kernel<<<gemmGrid, 256, GEMM_SMEM>>>(wt, o1T, pidx, pw,
        dcn_b2, bn_g2, bn_b2, bn_m2, bn_v2, out, 0);

    // channel attention
    pool_kernel<<<Bv * Cv, 256>>>(out, mxp, avp);
    cam_kernel<<<Bv, 128>>>(mxp, avp, cam_w1, cam_w2, chp);
    scale_kernel<<<scaleGrid, 256>>>(out, chp);
}

// round 14
// speedup vs baseline: 1.0160x; 1.0160x over previous
#include <cuda_runtime.h>
#include <cuda_bf16.h>
#include <cstdint>
#include <math.h>

#define Bv 8
#define Cv 128
#define Hv 96
#define Wv 96
#define HWv (Hv * Wv)        // 9216
#define Kv 9
#define KD (Cv * Kv)         // 1152
#define OCOFF 27
#define EPSv 1e-5f

// ---------------- scratch (device globals; no runtime allocation) ----------------
__device__ float  g_xT[(size_t)Bv * HWv * Cv];   // hw-major input (layer 1)
__device__ float  g_o1T[(size_t)Bv * HWv * Cv];  // hw-major layer-1 output
__device__ float  g_wt[Cv * KD];                 // transposed dcn weight, tf32
__device__ float  g_wt2[32 * KD];                // transposed offset weight (27->32 pad), tf32
__device__ int4   g_pidx[Bv * Kv * HWv];
__device__ float4 g_pw[Bv * Kv * HWv];
__device__ float  g_mx[Bv * Cv];
__device__ float  g_av[Bv * Cv];
__device__ float  g_ch[Bv * Cv];

__device__ __forceinline__ float to_tf32(float v) {
    float r;
    asm("cvt.rna.tf32.f32 %0, %1;" : "=f"(r) : "f"(v));
    return r;
}

__device__ __forceinline__ void cpa16(float* sdst, const float* gsrc) {
    unsigned int s = (unsigned int)__cvta_generic_to_shared(sdst);
    asm volatile("cp.async.cg.shared.global [%0], [%1], 16;\n" :: "r"(s), "l"(gsrc));
}

__device__ __forceinline__ void mma_tf32(float* d, const float* a, const float* bfr) {
    asm volatile(
        "mma.sync.aligned.m16n8k8.row.col.f32.tf32.tf32.f32 "
        "{%0,%1,%2,%3}, {%4,%5,%6,%7}, {%8,%9}, {%0,%1,%2,%3};\n"
        : "+f"(d[0]), "+f"(d[1]), "+f"(d[2]), "+f"(d[3])
        : "r"(__float_as_uint(a[0])), "r"(__float_as_uint(a[1])),
          "r"(__float_as_uint(a[2])), "r"(__float_as_uint(a[3])),
          "r"(__float_as_uint(bfr[0])), "r"(__float_as_uint(bfr[1])));
}

// ---------------- transpose x: (C, HW) -> (HW, C) per batch ----------------
__global__ void transpose_kernel(const float* __restrict__ src, float* __restrict__ dst) {
    __shared__ float tile[32][33];
    const int b = blockIdx.z;
    const int hw0 = blockIdx.x * 32;
    const int c0  = blockIdx.y * 32;
    const int tx = threadIdx.x, ty = threadIdx.y;   // (32, 8)
    const float* s = src + (size_t)b * Cv * HWv;
    float* d = dst + (size_t)b * HWv * Cv;
#pragma unroll
    for (int i = 0; i < 4; i++)
        tile[ty + i * 8][tx] = s[(size_t)(c0 + ty + i * 8) * HWv + hw0 + tx];
    __syncthreads();
#pragma unroll
    for (int i = 0; i < 4; i++)
        d[(size_t)(hw0 + ty + i * 8) * Cv + c0 + tx] = tile[tx][ty + i * 8];
}

// ---------------- weight transposes (tf32-rounded) ----------------
__global__ void wtrans_kernel(const float* __restrict__ w, float* __restrict__ wt) {
    int t = blockIdx.x * blockDim.x + threadIdx.x;
    if (t >= Cv * KD) return;
    int o = t / KD, r = t % KD, k = r / Cv, i = r % Cv;
    wt[t] = to_tf32(w[((size_t)o * Cv + i) * Kv + k]);
}

__global__ void wtrans_off_kernel(const float* __restrict__ w, float* __restrict__ wt2) {
    int t = blockIdx.x * blockDim.x + threadIdx.x;
    if (t >= 32 * KD) return;
    int o = t / KD, r = t % KD, k = r / Cv, i = r % Cv;
    wt2[t] = (o < OCOFF) ? to_tf32(w[((size_t)o * Cv + i) * Kv + k]) : 0.f;
}

// ================= tile constants =================
#define TBN 128
#define TBK 32
#define NT (KD / TBK)        // 36
#define AS_STRIDE 36
#define BS_STRIDE 36          // n-major B: Bs[n][k]
#define STAGE_A (128 * AS_STRIDE)      // 4608
#define STAGE_B (128 * BS_STRIDE)      // 4608
#define STAGE_F (STAGE_A + STAGE_B)    // 9216
#define GEMM_SMEM (2 * STAGE_F * 4)    // 73728 B

#define OSTAGE_A (32 * AS_STRIDE)          // 1152
#define OSTAGE_F (OSTAGE_A + STAGE_B)      // 5760
#define OGEMM_SMEM (2 * OSTAGE_F * 4)      // 46080 B
#define SOM_STRIDE 132

// ---------------- offset GEMM (tf32, reads xT) + fused prep ----------------
__global__ void __launch_bounds__(256)
off_gemm_prep_kernel(const float* __restrict__ wt2,   // (32, KD) tf32
                     const float* __restrict__ xT,    // (B, HW, C)
                     const float* __restrict__ off_b, // (27)
                     int4* __restrict__ pidx,
                     float4* __restrict__ pw) {
    extern __shared__ float smem[];
    const int b   = blockIdx.y;
    const int n0  = blockIdx.x * TBN;
    const int tid = threadIdx.x;
    const int warp = tid >> 5, lane = tid & 31;
    const int gid = lane >> 2, tig = lane & 3;
    const int q  = lane >> 3, cl = lane & 7;
    const int wm = (warp & 1) * 16;
    const int wn = (warp >> 1) * 32;
    const float* xb = xT + (size_t)b * HWv * Cv;

    float acc[4][4];
#pragma unroll
    for (int j = 0; j < 4; j++)
#pragma unroll
        for (int c = 0; c < 4; c++) acc[j][c] = 0.f;

    auto issueA = [&](int kt) {
        float* As = smem + (kt & 1) * OSTAGE_F;
        const int k0 = kt * TBK;
        int m = tid >> 3, kkv = (tid & 7) << 2;
        cpa16(As + m * AS_STRIDE + kkv, wt2 + (size_t)m * KD + k0 + kkv);
        asm volatile("cp.async.commit_group;\n" ::);
    };

    auto buildB = [&](int kt) {
        const int kp = kt >> 2, cg = kt & 3;
        const int dyk = kp / 3 - 1, dxk = kp % 3 - 1;
        float* Bs = smem + (kt & 1) * OSTAGE_F + OSTAGE_A;
#pragma unroll
        for (int r = 0; r < 4; r++) {
            int hwl = warp * 16 + r * 4 + q;
            int hw = n0 + hwl;
            int h = hw / Wv, w = hw % Wv;
            bool valid = ((unsigned)(h + dyk) < Hv) && ((unsigned)(w + dxk) < Wv);
            float4 v = make_float4(0.f, 0.f, 0.f, 0.f);
            if (valid) {
                int idx = hw + dyk * Wv + dxk;
                v = *(const float4*)(xb + (size_t)idx * Cv + cg * 32 + cl * 4);
            }
            v.x = to_tf32(v.x); v.y = to_tf32(v.y);
            v.z = to_tf32(v.z); v.w = to_tf32(v.w);
            *(float4*)(Bs + hwl * BS_STRIDE + cl * 4) = v;
        }
    };

    // race-free single-barrier pipeline:
    // writes for stage kt+1 happen while mma(kt) runs (disjoint buffers);
    // every thread waits its cp.async group BEFORE the barrier, so the
    // barrier publishes the full A stage to all warps.
    issueA(0);
    buildB(0);
    asm volatile("cp.async.wait_group 0;\n" ::);
    __syncthreads();
    for (int kt = 0; kt < NT; kt++) {
        if (kt + 1 < NT) {
            issueA(kt + 1);
            buildB(kt + 1);
        }
        const float* As = smem + (kt & 1) * OSTAGE_F;
        const float* Bs = As + OSTAGE_A;
#pragma unroll
        for (int s = 0; s < 4; s++) {
            const int ks = s * 8;
            float afr[4];
            int m = wm + gid;
            afr[0] = As[m * AS_STRIDE + ks + tig];
            afr[1] = As[(m + 8) * AS_STRIDE + ks + tig];
            afr[2] = As[m * AS_STRIDE + ks + tig + 4];
            afr[3] = As[(m + 8) * AS_STRIDE + ks + tig + 4];
            float bfr[4][2];
#pragma unroll
            for (int nj = 0; nj < 4; nj++) {
                int n = wn + nj * 8 + gid;
                bfr[nj][0] = Bs[n * BS_STRIDE + ks + tig];
                bfr[nj][1] = Bs[n * BS_STRIDE + ks + tig + 4];
            }
#pragma unroll
            for (int nj = 0; nj < 4; nj++)
                mma_tf32(acc[nj], afr, bfr[nj]);
        }
        if (kt + 1 < NT) asm volatile("cp.async.wait_group 0;\n" ::);
        __syncthreads();
    }

    // ---- stage om tile (32 x 128) into smem with bias ----
    float* som = smem;
    {
        int o0 = wm + gid, o1r = o0 + 8;
        float bb0 = (o0 < OCOFF) ? off_b[o0] : 0.f;
        float bb1 = (o1r < OCOFF) ? off_b[o1r] : 0.f;
#pragma unroll
        for (int nj = 0; nj < 4; nj++) {
            int ncol = wn + nj * 8 + 2 * tig;
            som[o0 * SOM_STRIDE + ncol]      = acc[nj][0] + bb0;
            som[o0 * SOM_STRIDE + ncol + 1]  = acc[nj][1] + bb0;
            som[o1r * SOM_STRIDE + ncol]     = acc[nj][2] + bb1;
            som[o1r * SOM_STRIDE + ncol + 1] = acc[nj][3] + bb1;
        }
    }
    __syncthreads();

    // ---- prep: pidx / pw for all (k, col) of this tile ----
    for (int t = tid; t < Kv * TBN; t += 256) {
        int k = t / TBN, col = t % TBN;
        int phw = n0 + col;
        int ph = phw / Wv, pwd = phw % Wv;
        float dy = som[(2 * k) * SOM_STRIDE + col];
        float dx = som[(2 * k + 1) * SOM_STRIDE + col];
        float msk = 1.f / (1.f + expf(-som[(18 + k) * SOM_STRIDE + col]));

        float py = (float)ph - 1.f + (float)(k / 3) + dy;
        float px = (float)pwd - 1.f + (float)(k % 3) + dx;
        float y0f = floorf(py), x0f = floorf(px);
        float wy1 = py - y0f, wx1 = px - x0f;
        int y0 = (int)y0f, x0 = (int)x0f;
        int y1 = y0 + 1, x1 = x0 + 1;

        float w00 = (1.f - wy1) * (1.f - wx1) * msk;
        float w01 = (1.f - wy1) * wx1 * msk;
        float w10 = wy1 * (1.f - wx1) * msk;
        float w11 = wy1 * wx1 * msk;

        bool vy0 = (y0 >= 0 && y0 < Hv), vy1 = (y1 >= 0 && y1 < Hv);
        bool vx0 = (x0 >= 0 && x0 < Wv), vx1 = (x1 >= 0 && x1 < Wv);
        if (!(vy0 && vx0)) w00 = 0.f;
        if (!(vy0 && vx1)) w01 = 0.f;
        if (!(vy1 && vx0)) w10 = 0.f;
        if (!(vy1 && vx1)) w11 = 0.f;

        int iy0 = min(max(y0, 0), Hv - 1), iy1 = min(max(y1, 0), Hv - 1);
        int ix0 = min(max(x0, 0), Wv - 1), ix1 = min(max(x1, 0), Wv - 1);

        size_t gi = ((size_t)b * Kv + k) * HWv + phw;
        pidx[gi] = make_int4(iy0 * Wv + ix0, iy0 * Wv + ix1,
                             iy1 * Wv + ix0, iy1 * Wv + ix1);
        pw[gi]   = make_float4(w00, w01, w10, w11);
    }
}

// ---------------- fused gather(xT) + tf32 GEMM + bias/BN/ReLU ----------------
__global__ void __launch_bounds__(256, 2)
fused_dcn_gemm_kernel(const float* __restrict__ wt,     // (C, KD) tf32
                      const float* __restrict__ xT,     // (B, HW, C)
                      const int4*  __restrict__ pidx,
                      const float4* __restrict__ pw,
                      const float* __restrict__ bias,
                      const float* __restrict__ bn_g,
                      const float* __restrict__ bn_b,
                      const float* __restrict__ bn_m,
                      const float* __restrict__ bn_v,
                      float* __restrict__ out,          // (B,C,HW) or (B,HW,C)
                      int transposed) {
    extern __shared__ float smem[];
    const int b   = blockIdx.y;
    const int n0  = blockIdx.x * TBN;
    const int tid = threadIdx.x;
    const int warp = tid >> 5, lane = tid & 31;
    const int gid = lane >> 2, tig = lane & 3;
    const int q  = lane >> 3, cl = lane & 7;
    const int wm = (warp & 1) * 64;
    const int wn = (warp >> 1) * 32;
    const float* xb = xT + (size_t)b * HWv * Cv;

    float acc[4][4][4];
#pragma unroll
    for (int i = 0; i < 4; i++)
#pragma unroll
        for (int j = 0; j < 4; j++)
#pragma unroll
            for (int c = 0; c < 4; c++) acc[i][j][c] = 0.f;

    auto issueA = [&](int kt) {
        float* As = smem + (kt & 1) * STAGE_F;
        const int k0 = kt * TBK;
#pragma unroll
        for (int r = 0; r < 4; r++) {
            int e = tid + r * 256;
            int m = e >> 3, kkv = (e & 7) << 2;
            cpa16(As + m * AS_STRIDE + kkv, wt + (size_t)m * KD + k0 + kkv);
        }
        asm volatile("cp.async.commit_group;\n" ::);
    };

    auto buildB = [&](int kt) {
        const int kp = kt >> 2, cg = kt & 3;
        float* Bs = smem + (kt & 1) * STAGE_F + STAGE_A;
#pragma unroll
        for (int r = 0; r < 4; r++) {
            int hwl = warp * 16 + r * 4 + q;
            size_t pbase = ((size_t)b * Kv + kp) * HWv + n0 + hwl;
            int4   id4 = __ldg(pidx + pbase);
            float4 w4  = __ldg(pw + pbase);
            const float* base = xb + cg * 32 + cl * 4;
            float4 c00 = *(const float4*)(base + (size_t)id4.x * Cv);
            float4 c01 = *(const float4*)(base + (size_t)id4.y * Cv);
            float4 c10 = *(const float4*)(base + (size_t)id4.z * Cv);
            float4 c11 = *(const float4*)(base + (size_t)id4.w * Cv);
            float4 v;
            v.x = to_tf32(w4.x * c00.x + w4.y * c01.x + w4.z * c10.x + w4.w * c11.x);
            v.y = to_tf32(w4.x * c00.y + w4.y * c01.y + w4.z * c10.y + w4.w * c11.y);
            v.z = to_tf32(w4.x * c00.z + w4.y * c01.z + w4.z * c10.z + w4.w * c11.z);
            v.w = to_tf32(w4.x * c00.w + w4.y * c01.w + w4.z * c10.w + w4.w * c11.w);
            *(float4*)(Bs + hwl * BS_STRIDE + cl * 4) = v;
        }
    };

    // race-free single-barrier pipeline (see off_gemm_prep_kernel comment)
    issueA(0);
    buildB(0);
    asm volatile("cp.async.wait_group 0;\n" ::);
    __syncthreads();
    for (int kt = 0; kt < NT; kt++) {
        if (kt + 1 < NT) {
            issueA(kt + 1);
            buildB(kt + 1);
        }
        const float* As = smem + (kt & 1) * STAGE_F;
        const float* Bs = As + STAGE_A;
#pragma unroll
        for (int s = 0; s < 4; s++) {
            const int ks = s * 8;
            float afr[4][4];
#pragma unroll
            for (int mi = 0; mi < 4; mi++) {
                int m = wm + mi * 16 + gid;
                afr[mi][0] = As[m * AS_STRIDE + ks + tig];
                afr[mi][1] = As[(m + 8) * AS_STRIDE + ks + tig];
                afr[mi][2] = As[m * AS_STRIDE + ks + tig + 4];
                afr[mi][3] = As[(m + 8) * AS_STRIDE + ks + tig + 4];
            }
            float bfr[4][2];
#pragma unroll
            for (int nj = 0; nj < 4; nj++) {
                int n = wn + nj * 8 + gid;
                bfr[nj][0] = Bs[n * BS_STRIDE + ks + tig];
                bfr[nj][1] = Bs[n * BS_STRIDE + ks + tig + 4];
            }
#pragma unroll
            for (int mi = 0; mi < 4; mi++)
#pragma unroll
                for (int nj = 0; nj < 4; nj++)
                    mma_tf32(acc[mi][nj], afr[mi], bfr[nj]);
        }
        if (kt + 1 < NT) asm volatile("cp.async.wait_group 0;\n" ::);
        __syncthreads();
    }

    // ---- epilogue: bias + BN + ReLU (direct stores) ----
#pragma unroll
    for (int mi = 0; mi < 4; mi++) {
        int o0 = wm + mi * 16 + gid;
        int o1r = o0 + 8;
        float sc0 = bn_g[o0]  * rsqrtf(bn_v[o0]  + EPSv);
        float sc1 = bn_g[o1r] * rsqrtf(bn_v[o1r] + EPSv);
        float bb0 = bias[o0] - bn_m[o0], bb1 = bias[o1r] - bn_m[o1r];
        float bt0 = bn_b[o0], bt1 = bn_b[o1r];
#pragma unroll
        for (int nj = 0; nj < 4; nj++) {
            int ncol = n0 + wn + nj * 8 + 2 * tig;
            float v00 = fmaxf((acc[mi][nj][0] + bb0) * sc0 + bt0, 0.f);
            float v01 = fmaxf((acc[mi][nj][1] + bb0) * sc0 + bt0, 0.f);
            float v10 = fmaxf((acc[mi][nj][2] + bb1) * sc1 + bt1, 0.f);
            float v11 = fmaxf((acc[mi][nj][3] + bb1) * sc1 + bt1, 0.f);
            if (transposed) {
                float* ob = out + (size_t)b * HWv * Cv;
                ob[(size_t)(ncol)     * Cv + o0]  = v00;
                ob[(size_t)(ncol + 1) * Cv + o0]  = v01;
                ob[(size_t)(ncol)     * Cv + o1r] = v10;
                ob[(size_t)(ncol + 1) * Cv + o1r] = v11;
            } else {
                *(float2*)(out + ((size_t)b * Cv + o0)  * HWv + ncol) = make_float2(v00, v01);
                *(float2*)(out + ((size_t)b * Cv + o1r) * HWv + ncol) = make_float2(v10, v11);
            }
        }
    }
}

// ---------------- global max/mean pool per (b,c) ----------------
__global__ void pool_kernel(const float* __restrict__ x,
                            float* __restrict__ mx, float* __restrict__ av) {
    int bc = blockIdx.x;
    const float* p = x + (size_t)bc * HWv;
    float vmax = -3.4e38f, vsum = 0.f;
    for (int i = threadIdx.x; i < HWv; i += 256) {
        float t = p[i];
        vmax = fmaxf(vmax, t);
        vsum += t;
    }
    __shared__ float sm[256], ss[256];
    sm[threadIdx.x] = vmax; ss[threadIdx.x] = vsum;
    __syncthreads();
    for (int s = 128; s > 0; s >>= 1) {
        if (threadIdx.x < s) {
            sm[threadIdx.x] = fmaxf(sm[threadIdx.x], sm[threadIdx.x + s]);
            ss[threadIdx.x] += ss[threadIdx.x + s];
        }
        __syncthreads();
    }
    if (threadIdx.x == 0) { mx[bc] = sm[0]; av[bc] = ss[0] * (1.f / HWv); }
}

// ---------------- channel-attention MLP ----------------
__global__ void cam_kernel(const float* __restrict__ mx, const float* __restrict__ av,
                           const float* __restrict__ w1,   // (32,128)
                           const float* __restrict__ w2,   // (128,32)
                           float* __restrict__ ch) {
    int b = blockIdx.x;
    int tid = threadIdx.x;
    __shared__ float smx[128], sav[128], sh[32];
    smx[tid] = mx[b * 128 + tid];
    sav[tid] = av[b * 128 + tid];
    __syncthreads();
    if (tid < 32) {
        float a = 0.f, c = 0.f;
        for (int i = 0; i < 128; i++) {
            float wv = w1[tid * 128 + i];
            a = fmaf(smx[i], wv, a);
            c = fmaf(sav[i], wv, c);
        }
        sh[tid] = fmaxf(a, 0.f) + fmaxf(c, 0.f);
    }
    __syncthreads();
    float o = 0.f;
#pragma unroll
    for (int j = 0; j < 32; j++) o = fmaf(sh[j], w2[tid * 32 + j], o);
    ch[b * 128 + tid] = 1.f / (1.f + expf(-o));
}

// ---------------- in-place channel scale ----------------
__global__ void scale_kernel(float* __restrict__ out, const float* __restrict__ ch) {
    size_t t = (size_t)blockIdx.x * blockDim.x + threadIdx.x;
    if (t >= (size_t)Bv * Cv * HWv) return;
    out[t] *= ch[t / HWv];
}

// ---------------- launch ----------------
extern "C" void kernel_launch(void* const* d_in, const int* in_sizes, int n_in,
                              void* d_out, int out_size) {
    const float* x      = (const float*)d_in[0];
    const float* off_w1 = (const float*)d_in[1];
    const float* off_b1 = (const float*)d_in[2];
    const float* dcn_w1 = (const float*)d_in[3];
    const float* dcn_b1 = (const float*)d_in[4];
    const float* bn_g1  = (const float*)d_in[5];
    const float* bn_b1  = (const float*)d_in[6];
    const float* bn_m1  = (const float*)d_in[7];
    const float* bn_v1  = (const float*)d_in[8];
    const float* off_w2 = (const float*)d_in[9];
    const float* off_b2 = (const float*)d_in[10];
    const float* dcn_w2 = (const float*)d_in[11];
    const float* dcn_b2 = (const float*)d_in[12];
    const float* bn_g2  = (const float*)d_in[13];
    const float* bn_b2  = (const float*)d_in[14];
    const float* bn_m2  = (const float*)d_in[15];
    const float* bn_v2  = (const float*)d_in[16];
    const float* cam_w1 = (const float*)d_in[17];
    const float* cam_w2 = (const float*)d_in[18];
    float* out = (float*)d_out;

    float *xT, *o1T, *wt, *wt2, *mxp, *avp, *chp;
    int4 *pidx; float4 *pw;
    cudaGetSymbolAddress((void**)&xT,   g_xT);
    cudaGetSymbolAddress((void**)&o1T,  g_o1T);
    cudaGetSymbolAddress((void**)&wt,   g_wt);
    cudaGetSymbolAddress((void**)&wt2,  g_wt2);
    cudaGetSymbolAddress((void**)&pidx, g_pidx);
    cudaGetSymbolAddress((void**)&pw,   g_pw);
    cudaGetSymbolAddress((void**)&mxp,  g_mx);
    cudaGetSymbolAddress((void**)&avp,  g_av);
    cudaGetSymbolAddress((void**)&chp,  g_ch);

    cudaFuncSetAttribute(fused_dcn_gemm_kernel,
                         cudaFuncAttributeMaxDynamicSharedMemorySize, GEMM_SMEM);
    cudaFuncSetAttribute(off_gemm_prep_kernel,
                         cudaFuncAttributeMaxDynamicSharedMemorySize, OGEMM_SMEM);

    int  wtGrid  = (Cv * KD + 255) / 256;
    int  wt2Grid = (32 * KD + 255) / 256;
    dim3 trGrid(HWv / 32, Cv / 32, Bv);
    dim3 trBlk(32, 8);
    dim3 gemmGrid(HWv / TBN, Bv);
    int  scaleGrid = (Bv * Cv * HWv + 255) / 256;

    // layer 1 (writes o1T hw-major directly)
    transpose_kernel<<<trGrid, trBlk>>>(x, xT);
    wtrans_off_kernel<<<wt2Grid, 256>>>(off_w1, wt2);
    wtrans_kernel<<<wtGrid, 256>>>(dcn_w1, wt);
    off_gemm_prep_kernel<<<gemmGrid, 256, OGEMM_SMEM>>>(wt2, xT, off_b1, pidx, pw);
    fused_dcn_gemm_kernel<<<gemmGrid, 256, GEMM_SMEM>>>(wt, xT, pidx, pw,
        dcn_b1, bn_g1, bn_b1, bn_m1, bn_v1, o1T, 1);

    // layer 2 (writes channel-major final)
    wtrans_off_kernel<<<wt2Grid, 256>>>(off_w2, wt2);
    wtrans_kernel<<<wtGrid, 256>>>(dcn_w2, wt);
    off_gemm_prep_kernel<<<gemmGrid, 256, OGEMM_SMEM>>>(wt2, o1T, off_b2, pidx, pw);
    fused_dcn_gemm_kernel<<<gemmGrid, 256, GEMM_SMEM>>>(wt, o1T, pidx, pw,
        dcn_b2, bn_g2, bn_b2, bn_m2, bn_v2, out, 0);

    // channel attention
    pool_kernel<<<Bv * Cv, 256>>>(out, mxp, avp);
    cam_kernel<<<Bv, 128>>>(mxp, avp, cam_w1, cam_w2, chp);
    scale_kernel<<<scaleGrid, 256>>>(out, chp);
}

// round 15
// speedup vs baseline: 1.0421x; 1.0256x over previous
#include <cuda_runtime.h>
#include <cuda_bf16.h>
#include <cstdint>
#include <math.h>

#define Bv 8
#define Cv 128
#define Hv 96
#define Wv 96
#define HWv (Hv * Wv)        // 9216
#define Kv 9
#define KD (Cv * Kv)         // 1152
#define OCOFF 27
#define EPSv 1e-5f

// ---------------- scratch (device globals; no runtime allocation) ----------------
__device__ float  g_xT[(size_t)Bv * HWv * Cv];   // hw-major input (layer 1)
__device__ float  g_o1T[(size_t)Bv * HWv * Cv];  // hw-major layer-1 output
__device__ float  g_wt1[Cv * KD];                // dcn weight layer1, tf32
__device__ float  g_wt2d[Cv * KD];               // dcn weight layer2, tf32
__device__ float  g_ow1[32 * KD];                // offset weight layer1 (padded), tf32
__device__ float  g_ow2[32 * KD];                // offset weight layer2 (padded), tf32
__device__ int4   g_pidx[Bv * Kv * HWv];
__device__ float4 g_pw[Bv * Kv * HWv];
__device__ float  g_mx[Bv * Cv];
__device__ float  g_av[Bv * Cv];
__device__ float  g_ch[Bv * Cv];

__device__ __forceinline__ float to_tf32(float v) {
    float r;
    asm("cvt.rna.tf32.f32 %0, %1;" : "=f"(r) : "f"(v));
    return r;
}

__device__ __forceinline__ void cpa16(float* sdst, const float* gsrc) {
    unsigned int s = (unsigned int)__cvta_generic_to_shared(sdst);
    asm volatile("cp.async.cg.shared.global [%0], [%1], 16;\n" :: "r"(s), "l"(gsrc));
}

__device__ __forceinline__ void mma_tf32(float* d, const float* a, const float* bfr) {
    asm volatile(
        "mma.sync.aligned.m16n8k8.row.col.f32.tf32.tf32.f32 "
        "{%0,%1,%2,%3}, {%4,%5,%6,%7}, {%8,%9}, {%0,%1,%2,%3};\n"
        : "+f"(d[0]), "+f"(d[1]), "+f"(d[2]), "+f"(d[3])
        : "r"(__float_as_uint(a[0])), "r"(__float_as_uint(a[1])),
          "r"(__float_as_uint(a[2])), "r"(__float_as_uint(a[3])),
          "r"(__float_as_uint(bfr[0])), "r"(__float_as_uint(bfr[1])));
}

// ---------------- transpose x: (C, HW) -> (HW, C) per batch ----------------
__global__ void transpose_kernel(const float* __restrict__ src, float* __restrict__ dst) {
    __shared__ float tile[32][33];
    const int b = blockIdx.z;
    const int hw0 = blockIdx.x * 32;
    const int c0  = blockIdx.y * 32;
    const int tx = threadIdx.x, ty = threadIdx.y;   // (32, 8)
    const float* s = src + (size_t)b * Cv * HWv;
    float* d = dst + (size_t)b * HWv * Cv;
#pragma unroll
    for (int i = 0; i < 4; i++)
        tile[ty + i * 8][tx] = s[(size_t)(c0 + ty + i * 8) * HWv + hw0 + tx];
    __syncthreads();
#pragma unroll
    for (int i = 0; i < 4; i++)
        d[(size_t)(hw0 + ty + i * 8) * Cv + c0 + tx] = tile[tx][ty + i * 8];
}

// ---------------- merged weight transposes (tf32) ----------------
__global__ void prep_weights_kernel(const float* __restrict__ dcn_w1,
                                    const float* __restrict__ dcn_w2,
                                    const float* __restrict__ off_w1,
                                    const float* __restrict__ off_w2,
                                    float* __restrict__ wt1, float* __restrict__ wt2d,
                                    float* __restrict__ ow1, float* __restrict__ ow2) {
    int t = blockIdx.x * blockDim.x + threadIdx.x;
    if (t < Cv * KD) {
        int o = t / KD, r = t % KD, k = r / Cv, i = r % Cv;
        size_t si = ((size_t)o * Cv + i) * Kv + k;
        wt1[t]  = to_tf32(dcn_w1[si]);
        wt2d[t] = to_tf32(dcn_w2[si]);
    }
    if (t < 32 * KD) {
        int o = t / KD, r = t % KD, k = r / Cv, i = r % Cv;
        if (o < OCOFF) {
            size_t si = ((size_t)o * Cv + i) * Kv + k;
            ow1[t] = to_tf32(off_w1[si]);
            ow2[t] = to_tf32(off_w2[si]);
        } else { ow1[t] = 0.f; ow2[t] = 0.f; }
    }
}

// ================= tile constants =================
#define TBN 128
#define TBK 32
#define NT (KD / TBK)        // 36
#define AS_STRIDE 36
#define BS_STRIDE 36          // n-major B: Bs[n][k]
#define STAGE_A (128 * AS_STRIDE)      // 4608
#define STAGE_B (128 * BS_STRIDE)      // 4608
#define STAGE_F (STAGE_A + STAGE_B)    // 9216
#define GEMM_SMEM (2 * STAGE_F * 4)    // 73728 B

#define OSTAGE_A (32 * AS_STRIDE)          // 1152
#define OSTAGE_F (OSTAGE_A + STAGE_B)      // 5760
#define OGEMM_SMEM (2 * OSTAGE_F * 4)      // 46080 B
#define SOM_STRIDE 132

// ---------------- offset GEMM (tf32, reads xT) + fused prep ----------------
__global__ void __launch_bounds__(256)
off_gemm_prep_kernel(const float* __restrict__ wt2,   // (32, KD) tf32
                     const float* __restrict__ xT,    // (B, HW, C)
                     const float* __restrict__ off_b, // (27)
                     int4* __restrict__ pidx,
                     float4* __restrict__ pw) {
    extern __shared__ float smem[];
    const int b   = blockIdx.y;
    const int n0  = blockIdx.x * TBN;
    const int tid = threadIdx.x;
    const int warp = tid >> 5, lane = tid & 31;
    const int gid = lane >> 2, tig = lane & 3;
    const int q  = lane >> 3, cl = lane & 7;
    const int wm = (warp & 1) * 16;
    const int wn = (warp >> 1) * 32;
    const float* xb = xT + (size_t)b * HWv * Cv;

    float acc[4][4];
#pragma unroll
    for (int j = 0; j < 4; j++)
#pragma unroll
        for (int c = 0; c < 4; c++) acc[j][c] = 0.f;

    auto issueA = [&](int kt) {
        float* As = smem + (kt & 1) * OSTAGE_F;
        const int k0 = kt * TBK;
        int m = tid >> 3, kkv = (tid & 7) << 2;
        cpa16(As + m * AS_STRIDE + kkv, wt2 + (size_t)m * KD + k0 + kkv);
        asm volatile("cp.async.commit_group;\n" ::);
    };

    auto buildB = [&](int kt) {
        const int kp = kt >> 2, cg = kt & 3;
        const int dyk = kp / 3 - 1, dxk = kp % 3 - 1;
        float* Bs = smem + (kt & 1) * OSTAGE_F + OSTAGE_A;
#pragma unroll
        for (int r = 0; r < 4; r++) {
            int hwl = warp * 16 + r * 4 + q;
            int hw = n0 + hwl;
            int h = hw / Wv, w = hw % Wv;
            bool valid = ((unsigned)(h + dyk) < Hv) && ((unsigned)(w + dxk) < Wv);
            float4 v = make_float4(0.f, 0.f, 0.f, 0.f);
            if (valid) {
                int idx = hw + dyk * Wv + dxk;
                v = *(const float4*)(xb + (size_t)idx * Cv + cg * 32 + cl * 4);
            }
            v.x = to_tf32(v.x); v.y = to_tf32(v.y);
            v.z = to_tf32(v.z); v.w = to_tf32(v.w);
            *(float4*)(Bs + hwl * BS_STRIDE + cl * 4) = v;
        }
    };

    // race-free single-barrier pipeline:
    // writes for stage kt+1 happen while mma(kt) runs (disjoint buffers);
    // every thread waits its cp.async group BEFORE the barrier, so the
    // barrier publishes the full A stage to all warps.
    issueA(0);
    buildB(0);
    asm volatile("cp.async.wait_group 0;\n" ::);
    __syncthreads();
    for (int kt = 0; kt < NT; kt++) {
        if (kt + 1 < NT) {
            issueA(kt + 1);
            buildB(kt + 1);
        }
        const float* As = smem + (kt & 1) * OSTAGE_F;
        const float* Bs = As + OSTAGE_A;
#pragma unroll
        for (int s = 0; s < 4; s++) {
            const int ks = s * 8;
            float afr[4];
            int m = wm + gid;
            afr[0] = As[m * AS_STRIDE + ks + tig];
            afr[1] = As[(m + 8) * AS_STRIDE + ks + tig];
            afr[2] = As[m * AS_STRIDE + ks + tig + 4];
            afr[3] = As[(m + 8) * AS_STRIDE + ks + tig + 4];
            float bfr[4][2];
#pragma unroll
            for (int nj = 0; nj < 4; nj++) {
                int n = wn + nj * 8 + gid;
                bfr[nj][0] = Bs[n * BS_STRIDE + ks + tig];
                bfr[nj][1] = Bs[n * BS_STRIDE + ks + tig + 4];
            }
#pragma unroll
            for (int nj = 0; nj < 4; nj++)
                mma_tf32(acc[nj], afr, bfr[nj]);
        }
        if (kt + 1 < NT) asm volatile("cp.async.wait_group 0;\n" ::);
        __syncthreads();
    }

    // ---- stage om tile (32 x 128) into smem with bias ----
    float* som = smem;
    {
        int o0 = wm + gid, o1r = o0 + 8;
        float bb0 = (o0 < OCOFF) ? off_b[o0] : 0.f;
        float bb1 = (o1r < OCOFF) ? off_b[o1r] : 0.f;
#pragma unroll
        for (int nj = 0; nj < 4; nj++) {
            int ncol = wn + nj * 8 + 2 * tig;
            som[o0 * SOM_STRIDE + ncol]      = acc[nj][0] + bb0;
            som[o0 * SOM_STRIDE + ncol + 1]  = acc[nj][1] + bb0;
            som[o1r * SOM_STRIDE + ncol]     = acc[nj][2] + bb1;
            som[o1r * SOM_STRIDE + ncol + 1] = acc[nj][3] + bb1;
        }
    }
    __syncthreads();

    // ---- prep: pidx / pw for all (k, col) of this tile ----
    for (int t = tid; t < Kv * TBN; t += 256) {
        int k = t / TBN, col = t % TBN;
        int phw = n0 + col;
        int ph = phw / Wv, pwd = phw % Wv;
        float dy = som[(2 * k) * SOM_STRIDE + col];
        float dx = som[(2 * k + 1) * SOM_STRIDE + col];
        float msk = 1.f / (1.f + expf(-som[(18 + k) * SOM_STRIDE + col]));

        float py = (float)ph - 1.f + (float)(k / 3) + dy;
        float px = (float)pwd - 1.f + (float)(k % 3) + dx;
        float y0f = floorf(py), x0f = floorf(px);
        float wy1 = py - y0f, wx1 = px - x0f;
        int y0 = (int)y0f, x0 = (int)x0f;
        int y1 = y0 + 1, x1 = x0 + 1;

        float w00 = (1.f - wy1) * (1.f - wx1) * msk;
        float w01 = (1.f - wy1) * wx1 * msk;
        float w10 = wy1 * (1.f - wx1) * msk;
        float w11 = wy1 * wx1 * msk;

        bool vy0 = (y0 >= 0 && y0 < Hv), vy1 = (y1 >= 0 && y1 < Hv);
        bool vx0 = (x0 >= 0 && x0 < Wv), vx1 = (x1 >= 0 && x1 < Wv);
        if (!(vy0 && vx0)) w00 = 0.f;
        if (!(vy0 && vx1)) w01 = 0.f;
        if (!(vy1 && vx0)) w10 = 0.f;
        if (!(vy1 && vx1)) w11 = 0.f;

        int iy0 = min(max(y0, 0), Hv - 1), iy1 = min(max(y1, 0), Hv - 1);
        int ix0 = min(max(x0, 0), Wv - 1), ix1 = min(max(x1, 0), Wv - 1);

        size_t gi = ((size_t)b * Kv + k) * HWv + phw;
        pidx[gi] = make_int4(iy0 * Wv + ix0, iy0 * Wv + ix1,
                             iy1 * Wv + ix0, iy1 * Wv + ix1);
        pw[gi]   = make_float4(w00, w01, w10, w11);
    }
}

// ---------------- fused gather(xT) + tf32 GEMM + bias/BN/ReLU ----------------
__global__ void __launch_bounds__(256, 2)
fused_dcn_gemm_kernel(const float* __restrict__ wt,     // (C, KD) tf32
                      const float* __restrict__ xT,     // (B, HW, C)
                      const int4*  __restrict__ pidx,
                      const float4* __restrict__ pw,
                      const float* __restrict__ bias,
                      const float* __restrict__ bn_g,
                      const float* __restrict__ bn_b,
                      const float* __restrict__ bn_m,
                      const float* __restrict__ bn_v,
                      float* __restrict__ out,          // (B,C,HW) or (B,HW,C)
                      int transposed) {
    extern __shared__ float smem[];
    const int b   = blockIdx.y;
    const int n0  = blockIdx.x * TBN;
    const int tid = threadIdx.x;
    const int warp = tid >> 5, lane = tid & 31;
    const int gid = lane >> 2, tig = lane & 3;
    const int q  = lane >> 3, cl = lane & 7;
    const int wm = (warp & 1) * 64;
    const int wn = (warp >> 1) * 32;
    const float* xb = xT + (size_t)b * HWv * Cv;

    float acc[4][4][4];
#pragma unroll
    for (int i = 0; i < 4; i++)
#pragma unroll
        for (int j = 0; j < 4; j++)
#pragma unroll
            for (int c = 0; c < 4; c++) acc[i][j][c] = 0.f;

    auto issueA = [&](int kt) {
        float* As = smem + (kt & 1) * STAGE_F;
        const int k0 = kt * TBK;
#pragma unroll
        for (int r = 0; r < 4; r++) {
            int e = tid + r * 256;
            int m = e >> 3, kkv = (e & 7) << 2;
            cpa16(As + m * AS_STRIDE + kkv, wt + (size_t)m * KD + k0 + kkv);
        }
        asm volatile("cp.async.commit_group;\n" ::);
    };

    auto buildB = [&](int kt) {
        const int kp = kt >> 2, cg = kt & 3;
        float* Bs = smem + (kt & 1) * STAGE_F + STAGE_A;
#pragma unroll
        for (int r = 0; r < 4; r++) {
            int hwl = warp * 16 + r * 4 + q;
            size_t pbase = ((size_t)b * Kv + kp) * HWv + n0 + hwl;
            int4   id4 = __ldg(pidx + pbase);
            float4 w4  = __ldg(pw + pbase);
            const float* base = xb + cg * 32 + cl * 4;
            float4 c00 = *(const float4*)(base + (size_t)id4.x * Cv);
            float4 c01 = *(const float4*)(base + (size_t)id4.y * Cv);
            float4 c10 = *(const float4*)(base + (size_t)id4.z * Cv);
            float4 c11 = *(const float4*)(base + (size_t)id4.w * Cv);
            float4 v;
            v.x = to_tf32(w4.x * c00.x + w4.y * c01.x + w4.z * c10.x + w4.w * c11.x);
            v.y = to_tf32(w4.x * c00.y + w4.y * c01.y + w4.z * c10.y + w4.w * c11.y);
            v.z = to_tf32(w4.x * c00.z + w4.y * c01.z + w4.z * c10.z + w4.w * c11.z);
            v.w = to_tf32(w4.x * c00.w + w4.y * c01.w + w4.z * c10.w + w4.w * c11.w);
            *(float4*)(Bs + hwl * BS_STRIDE + cl * 4) = v;
        }
    };

    // race-free single-barrier pipeline (see off_gemm_prep_kernel comment)
    issueA(0);
    buildB(0);
    asm volatile("cp.async.wait_group 0;\n" ::);
    __syncthreads();
    for (int kt = 0; kt < NT; kt++) {
        if (kt + 1 < NT) {
            issueA(kt + 1);
            buildB(kt + 1);
        }
        const float* As = smem + (kt & 1) * STAGE_F;
        const float* Bs = As + STAGE_A;
#pragma unroll
        for (int s = 0; s < 4; s++) {
            const int ks = s * 8;
            float afr[4][4];
#pragma unroll
            for (int mi = 0; mi < 4; mi++) {
                int m = wm + mi * 16 + gid;
                afr[mi][0] = As[m * AS_STRIDE + ks + tig];
                afr[mi][1] = As[(m + 8) * AS_STRIDE + ks + tig];
                afr[mi][2] = As[m * AS_STRIDE + ks + tig + 4];
                afr[mi][3] = As[(m + 8) * AS_STRIDE + ks + tig + 4];
            }
            float bfr[4][2];
#pragma unroll
            for (int nj = 0; nj < 4; nj++) {
                int n = wn + nj * 8 + gid;
                bfr[nj][0] = Bs[n * BS_STRIDE + ks + tig];
                bfr[nj][1] = Bs[n * BS_STRIDE + ks + tig + 4];
            }
#pragma unroll
            for (int mi = 0; mi < 4; mi++)
#pragma unroll
                for (int nj = 0; nj < 4; nj++)
                    mma_tf32(acc[mi][nj], afr[mi], bfr[nj]);
        }
        if (kt + 1 < NT) asm volatile("cp.async.wait_group 0;\n" ::);
        __syncthreads();
    }

    // ---- epilogue: bias + BN + ReLU (direct stores) ----
#pragma unroll
    for (int mi = 0; mi < 4; mi++) {
        int o0 = wm + mi * 16 + gid;
        int o1r = o0 + 8;
        float sc0 = bn_g[o0]  * rsqrtf(bn_v[o0]  + EPSv);
        float sc1 = bn_g[o1r] * rsqrtf(bn_v[o1r] + EPSv);
        float bb0 = bias[o0] - bn_m[o0], bb1 = bias[o1r] - bn_m[o1r];
        float bt0 = bn_b[o0], bt1 = bn_b[o1r];
#pragma unroll
        for (int nj = 0; nj < 4; nj++) {
            int ncol = n0 + wn + nj * 8 + 2 * tig;
            float v00 = fmaxf((acc[mi][nj][0] + bb0) * sc0 + bt0, 0.f);
            float v01 = fmaxf((acc[mi][nj][1] + bb0) * sc0 + bt0, 0.f);
            float v10 = fmaxf((acc[mi][nj][2] + bb1) * sc1 + bt1, 0.f);
            float v11 = fmaxf((acc[mi][nj][3] + bb1) * sc1 + bt1, 0.f);
            if (transposed) {
                float* ob = out + (size_t)b * HWv * Cv;
                ob[(size_t)(ncol)     * Cv + o0]  = v00;
                ob[(size_t)(ncol + 1) * Cv + o0]  = v01;
                ob[(size_t)(ncol)     * Cv + o1r] = v10;
                ob[(size_t)(ncol + 1) * Cv + o1r] = v11;
            } else {
                *(float2*)(out + ((size_t)b * Cv + o0)  * HWv + ncol) = make_float2(v00, v01);
                *(float2*)(out + ((size_t)b * Cv + o1r) * HWv + ncol) = make_float2(v10, v11);
            }
        }
    }
}

// ---------------- global max/mean pool per (b,c) ----------------
__global__ void pool_kernel(const float* __restrict__ x,
                            float* __restrict__ mx, float* __restrict__ av) {
    int bc = blockIdx.x;
    const float* p = x + (size_t)bc * HWv;
    float vmax = -3.4e38f, vsum = 0.f;
    for (int i = threadIdx.x; i < HWv; i += 256) {
        float t = p[i];
        vmax = fmaxf(vmax, t);
        vsum += t;
    }
    __shared__ float sm[256], ss[256];
    sm[threadIdx.x] = vmax; ss[threadIdx.x] = vsum;
    __syncthreads();
    for (int s = 128; s > 0; s >>= 1) {
        if (threadIdx.x < s) {
            sm[threadIdx.x] = fmaxf(sm[threadIdx.x], sm[threadIdx.x + s]);
            ss[threadIdx.x] += ss[threadIdx.x + s];
        }
        __syncthreads();
    }
    if (threadIdx.x == 0) { mx[bc] = sm[0]; av[bc] = ss[0] * (1.f / HWv); }
}

// ---------------- channel-attention MLP ----------------
__global__ void cam_kernel(const float* __restrict__ mx, const float* __restrict__ av,
                           const float* __restrict__ w1,   // (32,128)
                           const float* __restrict__ w2,   // (128,32)
                           float* __restrict__ ch) {
    int b = blockIdx.x;
    int tid = threadIdx.x;
    __shared__ float smx[128], sav[128], sh[32];
    smx[tid] = mx[b * 128 + tid];
    sav[tid] = av[b * 128 + tid];
    __syncthreads();
    if (tid < 32) {
        float a = 0.f, c = 0.f;
        for (int i = 0; i < 128; i++) {
            float wv = w1[tid * 128 + i];
            a = fmaf(smx[i], wv, a);
            c = fmaf(sav[i], wv, c);
        }
        sh[tid] = fmaxf(a, 0.f) + fmaxf(c, 0.f);
    }
    __syncthreads();
    float o = 0.f;
#pragma unroll
    for (int j = 0; j < 32; j++) o = fmaf(sh[j], w2[tid * 32 + j], o);
    ch[b * 128 + tid] = 1.f / (1.f + expf(-o));
}

// ---------------- in-place channel scale (float4) ----------------
__global__ void scale_kernel(float4* __restrict__ out, const float* __restrict__ ch) {
    size_t t = (size_t)blockIdx.x * blockDim.x + threadIdx.x;
    if (t >= (size_t)Bv * Cv * HWv / 4) return;
    float s = ch[t / (HWv / 4)];
    float4 v = out[t];
    v.x *= s; v.y *= s; v.z *= s; v.w *= s;
    out[t] = v;
}

// ---------------- launch ----------------
extern "C" void kernel_launch(void* const* d_in, const int* in_sizes, int n_in,
                              void* d_out, int out_size) {
    const float* x      = (const float*)d_in[0];
    const float* off_w1 = (const float*)d_in[1];
    const float* off_b1 = (const float*)d_in[2];
    const float* dcn_w1 = (const float*)d_in[3];
    const float* dcn_b1 = (const float*)d_in[4];
    const float* bn_g1  = (const float*)d_in[5];
    const float* bn_b1  = (const float*)d_in[6];
    const float* bn_m1  = (const float*)d_in[7];
    const float* bn_v1  = (const float*)d_in[8];
    const float* off_w2 = (const float*)d_in[9];
    const float* off_b2 = (const float*)d_in[10];
    const float* dcn_w2 = (const float*)d_in[11];
    const float* dcn_b2 = (const float*)d_in[12];
    const float* bn_g2  = (const float*)d_in[13];
    const float* bn_b2  = (const float*)d_in[14];
    const float* bn_m2  = (const float*)d_in[15];
    const float* bn_v2  = (const float*)d_in[16];
    const float* cam_w1 = (const float*)d_in[17];
    const float* cam_w2 = (const float*)d_in[18];
    float* out = (float*)d_out;

    float *xT, *o1T, *wt1, *wt2d, *ow1, *ow2, *mxp, *avp, *chp;
    int4 *pidx; float4 *pw;
    cudaGetSymbolAddress((void**)&xT,   g_xT);
    cudaGetSymbolAddress((void**)&o1T,  g_o1T);
    cudaGetSymbolAddress((void**)&wt1,  g_wt1);
    cudaGetSymbolAddress((void**)&wt2d, g_wt2d);
    cudaGetSymbolAddress((void**)&ow1,  g_ow1);
    cudaGetSymbolAddress((void**)&ow2,  g_ow2);
    cudaGetSymbolAddress((void**)&pidx, g_pidx);
    cudaGetSymbolAddress((void**)&pw,   g_pw);
    cudaGetSymbolAddress((void**)&mxp,  g_mx);
    cudaGetSymbolAddress((void**)&avp,  g_av);
    cudaGetSymbolAddress((void**)&chp,  g_ch);

    cudaFuncSetAttribute(fused_dcn_gemm_kernel,
                         cudaFuncAttributeMaxDynamicSharedMemorySize, GEMM_SMEM);
    cudaFuncSetAttribute(off_gemm_prep_kernel,
                         cudaFuncAttributeMaxDynamicSharedMemorySize, OGEMM_SMEM);

    int  prepGrid = (Cv * KD + 255) / 256;
    dim3 trGrid(HWv / 32, Cv / 32, Bv);
    dim3 trBlk(32, 8);
    dim3 gemmGrid(HWv / TBN, Bv);
    int  scaleGrid = (Bv * Cv * HWv / 4 + 255) / 256;

    // weight prep (all layers, one launch)
    prep_weights_kernel<<<prepGrid, 256>>>(dcn_w1, dcn_w2, off_w1, off_w2,
                                           wt1, wt2d, ow1, ow2);

    // layer 1 (writes o1T hw-major directly)
    transpose_kernel<<<trGrid, trBlk>>>(x, xT);
    off_gemm_prep_kernel<<<gemmGrid, 256, OGEMM_SMEM>>>(ow1, xT, off_b1, pidx, pw);
    fused_dcn_gemm_kernel<<<gemmGrid, 256, GEMM_SMEM>>>(wt1, xT, pidx, pw,
        dcn_b1, bn_g1, bn_b1, bn_m1, bn_v1, o1T, 1);

    // layer 2 (writes channel-major final)
    off_gemm_prep_kernel<<<gemmGrid, 256, OGEMM_SMEM>>>(ow2, o1T, off_b2, pidx, pw);
    fused_dcn_gemm_kernel<<<gemmGrid, 256, GEMM_SMEM>>>(wt2d, o1T, pidx, pw,
        dcn_b2, bn_g2, bn_b2, bn_m2, bn_v2, out, 0);

    // channel attention
    pool_kernel<<<Bv * Cv, 256>>>(out, mxp, avp);
    cam_kernel<<<Bv, 128>>>(mxp, avp, cam_w1, cam_w2, chp);
    scale_kernel<<<scaleGrid, 256>>>((float4*)out, chp);
}

// round 17
// speedup vs baseline: 1.2854x; 1.2335x over previous
#include <cuda_runtime.h>
#include <cuda_bf16.h>
#include <cuda_fp16.h>
#include <cstdint>
#include <math.h>

#define Bv 8
#define Cv 128
#define Hv 96
#define Wv 96
#define HWv (Hv * Wv)        // 9216
#define Kv 9
#define KD (Cv * Kv)         // 1152
#define OCOFF 27
#define EPSv 1e-5f

// ---------------- scratch (device globals; no runtime allocation) ----------------
__device__ float  g_xT[(size_t)Bv * HWv * Cv];   // hw-major input (layer 1)
__device__ float  g_o1T[(size_t)Bv * HWv * Cv];  // hw-major layer-1 output
__device__ __half g_wt1h[Cv * KD];               // dcn weight layer1, fp16
__device__ __half g_wt2h[Cv * KD];               // dcn weight layer2, fp16
__device__ float  g_ow1[32 * KD];                // offset weight layer1 (padded), tf32
__device__ float  g_ow2[32 * KD];                // offset weight layer2 (padded), tf32
__device__ int4   g_pidx[Bv * Kv * HWv];
__device__ float4 g_pw[Bv * Kv * HWv];
__device__ float  g_mx[Bv * Cv];
__device__ float  g_av[Bv * Cv];
__device__ float  g_ch[Bv * Cv];

__device__ __forceinline__ float to_tf32(float v) {
    float r;
    asm("cvt.rna.tf32.f32 %0, %1;" : "=f"(r) : "f"(v));
    return r;
}

__device__ __forceinline__ void cpa16(void* sdst, const void* gsrc) {
    unsigned int s = (unsigned int)__cvta_generic_to_shared(sdst);
    asm volatile("cp.async.cg.shared.global [%0], [%1], 16;\n" :: "r"(s), "l"(gsrc));
}

__device__ __forceinline__ void mma_tf32(float* d, const float* a, const float* bfr) {
    asm volatile(
        "mma.sync.aligned.m16n8k8.row.col.f32.tf32.tf32.f32 "
        "{%0,%1,%2,%3}, {%4,%5,%6,%7}, {%8,%9}, {%0,%1,%2,%3};\n"
        : "+f"(d[0]), "+f"(d[1]), "+f"(d[2]), "+f"(d[3])
        : "r"(__float_as_uint(a[0])), "r"(__float_as_uint(a[1])),
          "r"(__float_as_uint(a[2])), "r"(__float_as_uint(a[3])),
          "r"(__float_as_uint(bfr[0])), "r"(__float_as_uint(bfr[1])));
}

__device__ __forceinline__ void mma_f16(float* d, const unsigned int* a, const unsigned int* b2) {
    asm volatile(
        "mma.sync.aligned.m16n8k16.row.col.f32.f16.f16.f32 "
        "{%0,%1,%2,%3}, {%4,%5,%6,%7}, {%8,%9}, {%0,%1,%2,%3};\n"
        : "+f"(d[0]), "+f"(d[1]), "+f"(d[2]), "+f"(d[3])
        : "r"(a[0]), "r"(a[1]), "r"(a[2]), "r"(a[3]), "r"(b2[0]), "r"(b2[1]));
}

// ---------------- transpose x: (C, HW) -> (HW, C) per batch ----------------
__global__ void transpose_kernel(const float* __restrict__ src, float* __restrict__ dst) {
    __shared__ float tile[32][33];
    const int b = blockIdx.z;
    const int hw0 = blockIdx.x * 32;
    const int c0  = blockIdx.y * 32;
    const int tx = threadIdx.x, ty = threadIdx.y;   // (32, 8)
    const float* s = src + (size_t)b * Cv * HWv;
    float* d = dst + (size_t)b * HWv * Cv;
#pragma unroll
    for (int i = 0; i < 4; i++)
        tile[ty + i * 8][tx] = s[(size_t)(c0 + ty + i * 8) * HWv + hw0 + tx];
    __syncthreads();
#pragma unroll
    for (int i = 0; i < 4; i++)
        d[(size_t)(hw0 + ty + i * 8) * Cv + c0 + tx] = tile[tx][ty + i * 8];
}

// ---------------- merged weight transposes (dcn->fp16, offset->tf32) ----------------
__global__ void prep_weights_kernel(const float* __restrict__ dcn_w1,
                                    const float* __restrict__ dcn_w2,
                                    const float* __restrict__ off_w1,
                                    const float* __restrict__ off_w2,
                                    __half* __restrict__ wt1h, __half* __restrict__ wt2h,
                                    float* __restrict__ ow1, float* __restrict__ ow2) {
    int t = blockIdx.x * blockDim.x + threadIdx.x;
    if (t < Cv * KD) {
        int o = t / KD, r = t % KD, k = r / Cv, i = r % Cv;
        size_t si = ((size_t)o * Cv + i) * Kv + k;
        wt1h[t] = __float2half_rn(dcn_w1[si]);
        wt2h[t] = __float2half_rn(dcn_w2[si]);
    }
    if (t < 32 * KD) {
        int o = t / KD, r = t % KD, k = r / Cv, i = r % Cv;
        if (o < OCOFF) {
            size_t si = ((size_t)o * Cv + i) * Kv + k;
            ow1[t] = to_tf32(off_w1[si]);
            ow2[t] = to_tf32(off_w2[si]);
        } else { ow1[t] = 0.f; ow2[t] = 0.f; }
    }
}

// ================= tile constants =================
#define TBN 128
#define TBK 32
#define NT (KD / TBK)        // 36

// off-gemm (tf32) constants
#define AS_STRIDE 36
#define BS_STRIDE 36
#define STAGE_B (128 * BS_STRIDE)
#define OSTAGE_A (32 * AS_STRIDE)
#define OSTAGE_F (OSTAGE_A + STAGE_B)
#define OGEMM_SMEM (2 * OSTAGE_F * 4)
#define SOM_STRIDE 132

// fused fp16 gemm constants (bytes)
#define AROWB 80                    // 32 halfs (64B) + 16B pad; 80 = 5*16 (16B-aligned rows)
#define HA_SZ (128 * AROWB)         // 10240 B per A stage
#define HSTAGE (2 * HA_SZ)          // 20480 B per stage (A + B)
#define FGEMM_SMEM (2 * HSTAGE)     // 40960 B

// ---------------- offset GEMM (tf32) + fused prep (unchanged from R15) ----------------
__global__ void __launch_bounds__(256)
off_gemm_prep_kernel(const float* __restrict__ wt2,
                     const float* __restrict__ xT,
                     const float* __restrict__ off_b,
                     int4* __restrict__ pidx,
                     float4* __restrict__ pw) {
    extern __shared__ float smem[];
    const int b   = blockIdx.y;
    const int n0  = blockIdx.x * TBN;
    const int tid = threadIdx.x;
    const int warp = tid >> 5, lane = tid & 31;
    const int gid = lane >> 2, tig = lane & 3;
    const int q  = lane >> 3, cl = lane & 7;
    const int wm = (warp & 1) * 16;
    const int wn = (warp >> 1) * 32;
    const float* xb = xT + (size_t)b * HWv * Cv;

    float acc[4][4];
#pragma unroll
    for (int j = 0; j < 4; j++)
#pragma unroll
        for (int c = 0; c < 4; c++) acc[j][c] = 0.f;

    auto issueA = [&](int kt) {
        float* As = smem + (kt & 1) * OSTAGE_F;
        const int k0 = kt * TBK;
        int m = tid >> 3, kkv = (tid & 7) << 2;
        cpa16(As + m * AS_STRIDE + kkv, wt2 + (size_t)m * KD + k0 + kkv);
        asm volatile("cp.async.commit_group;\n" ::);
    };

    auto buildB = [&](int kt) {
        const int kp = kt >> 2, cg = kt & 3;
        const int dyk = kp / 3 - 1, dxk = kp % 3 - 1;
        float* Bs = smem + (kt & 1) * OSTAGE_F + OSTAGE_A;
#pragma unroll
        for (int r = 0; r < 4; r++) {
            int hwl = warp * 16 + r * 4 + q;
            int hw = n0 + hwl;
            int h = hw / Wv, w = hw % Wv;
            bool valid = ((unsigned)(h + dyk) < Hv) && ((unsigned)(w + dxk) < Wv);
            float4 v = make_float4(0.f, 0.f, 0.f, 0.f);
            if (valid) {
                int idx = hw + dyk * Wv + dxk;
                v = *(const float4*)(xb + (size_t)idx * Cv + cg * 32 + cl * 4);
            }
            v.x = to_tf32(v.x); v.y = to_tf32(v.y);
            v.z = to_tf32(v.z); v.w = to_tf32(v.w);
            *(float4*)(Bs + hwl * BS_STRIDE + cl * 4) = v;
        }
    };

    issueA(0);
    buildB(0);
    asm volatile("cp.async.wait_group 0;\n" ::);
    __syncthreads();
    for (int kt = 0; kt < NT; kt++) {
        if (kt + 1 < NT) {
            issueA(kt + 1);
            buildB(kt + 1);
        }
        const float* As = smem + (kt & 1) * OSTAGE_F;
        const float* Bs = As + OSTAGE_A;
#pragma unroll
        for (int s = 0; s < 4; s++) {
            const int ks = s * 8;
            float afr[4];
            int m = wm + gid;
            afr[0] = As[m * AS_STRIDE + ks + tig];
            afr[1] = As[(m + 8) * AS_STRIDE + ks + tig];
            afr[2] = As[m * AS_STRIDE + ks + tig + 4];
            afr[3] = As[(m + 8) * AS_STRIDE + ks + tig + 4];
            float bfr[4][2];
#pragma unroll
            for (int nj = 0; nj < 4; nj++) {
                int n = wn + nj * 8 + gid;
                bfr[nj][0] = Bs[n * BS_STRIDE + ks + tig];
                bfr[nj][1] = Bs[n * BS_STRIDE + ks + tig + 4];
            }
#pragma unroll
            for (int nj = 0; nj < 4; nj++)
                mma_tf32(acc[nj], afr, bfr[nj]);
        }
        if (kt + 1 < NT) asm volatile("cp.async.wait_group 0;\n" ::);
        __syncthreads();
    }

    float* som = smem;
    {
        int o0 = wm + gid, o1r = o0 + 8;
        float bb0 = (o0 < OCOFF) ? off_b[o0] : 0.f;
        float bb1 = (o1r < OCOFF) ? off_b[o1r] : 0.f;
#pragma unroll
        for (int nj = 0; nj < 4; nj++) {
            int ncol = wn + nj * 8 + 2 * tig;
            som[o0 * SOM_STRIDE + ncol]      = acc[nj][0] + bb0;
            som[o0 * SOM_STRIDE + ncol + 1]  = acc[nj][1] + bb0;
            som[o1r * SOM_STRIDE + ncol]     = acc[nj][2] + bb1;
            som[o1r * SOM_STRIDE + ncol + 1] = acc[nj][3] + bb1;
        }
    }
    __syncthreads();

    for (int t = tid; t < Kv * TBN; t += 256) {
        int k = t / TBN, col = t % TBN;
        int phw = n0 + col;
        int ph = phw / Wv, pwd = phw % Wv;
        float dy = som[(2 * k) * SOM_STRIDE + col];
        float dx = som[(2 * k + 1) * SOM_STRIDE + col];
        float msk = 1.f / (1.f + expf(-som[(18 + k) * SOM_STRIDE + col]));

        float py = (float)ph - 1.f + (float)(k / 3) + dy;
        float px = (float)pwd - 1.f + (float)(k % 3) + dx;
        float y0f = floorf(py), x0f = floorf(px);
        float wy1 = py - y0f, wx1 = px - x0f;
        int y0 = (int)y0f, x0 = (int)x0f;
        int y1 = y0 + 1, x1 = x0 + 1;

        float w00 = (1.f - wy1) * (1.f - wx1) * msk;
        float w01 = (1.f - wy1) * wx1 * msk;
        float w10 = wy1 * (1.f - wx1) * msk;
        float w11 = wy1 * wx1 * msk;

        bool vy0 = (y0 >= 0 && y0 < Hv), vy1 = (y1 >= 0 && y1 < Hv);
        bool vx0 = (x0 >= 0 && x0 < Wv), vx1 = (x1 >= 0 && x1 < Wv);
        if (!(vy0 && vx0)) w00 = 0.f;
        if (!(vy0 && vx1)) w01 = 0.f;
        if (!(vy1 && vx0)) w10 = 0.f;
        if (!(vy1 && vx1)) w11 = 0.f;

        int iy0 = min(max(y0, 0), Hv - 1), iy1 = min(max(y1, 0), Hv - 1);
        int ix0 = min(max(x0, 0), Wv - 1), ix1 = min(max(x1, 0), Wv - 1);

        size_t gi = ((size_t)b * Kv + k) * HWv + phw;
        pidx[gi] = make_int4(iy0 * Wv + ix0, iy0 * Wv + ix1,
                             iy1 * Wv + ix0, iy1 * Wv + ix1);
        pw[gi]   = make_float4(w00, w01, w10, w11);
    }
}

// ---------------- fused gather(xT) + fp16 GEMM (m16n8k16, fp32 acc) + bias/BN/ReLU ----------------
__global__ void __launch_bounds__(256, 2)
fused_dcn_gemm_kernel(const __half* __restrict__ wth,   // (C, KD) fp16
                      const float* __restrict__ xT,     // (B, HW, C)
                      const int4*  __restrict__ pidx,
                      const float4* __restrict__ pw,
                      const float* __restrict__ bias,
                      const float* __restrict__ bn_g,
                      const float* __restrict__ bn_b,
                      const float* __restrict__ bn_m,
                      const float* __restrict__ bn_v,
                      float* __restrict__ out,          // (B,C,HW) or (B,HW,C)
                      int transposed) {
    extern __shared__ char smemb[];
    const int b   = blockIdx.y;
    const int n0  = blockIdx.x * TBN;
    const int tid = threadIdx.x;
    const int warp = tid >> 5, lane = tid & 31;
    const int gid = lane >> 2, tig = lane & 3;
    const int q  = lane >> 3, cl = lane & 7;
    const int wm = (warp & 1) * 64;
    const int wn = (warp >> 1) * 32;
    const float* xb = xT + (size_t)b * HWv * Cv;

    float acc[4][4][4];
#pragma unroll
    for (int i = 0; i < 4; i++)
#pragma unroll
        for (int j = 0; j < 4; j++)
#pragma unroll
            for (int c = 0; c < 4; c++) acc[i][j][c] = 0.f;

    // A: 128 rows x 32 halfs (64B) per tile, row stride 80B. 512 x 16B chunks.
    auto issueA = [&](int kt) {
        char* As = smemb + (kt & 1) * HSTAGE;
        const int k0 = kt * TBK;
#pragma unroll
        for (int r = 0; r < 2; r++) {
            int e = tid + r * 256;             // 0..511
            int m = e >> 2, ck = e & 3;        // row, 16B chunk (8 halfs)
            cpa16(As + m * AROWB + ck * 16, wth + (size_t)m * KD + k0 + ck * 8);
        }
        asm volatile("cp.async.commit_group;\n" ::);
    };

    // B: 128 rows (hw) x 32 halfs (ch), row stride 80B. Each thread: 4 rows x 4 ch.
    auto buildB = [&](int kt) {
        const int kp = kt >> 2, cg = kt & 3;
        char* Bs = smemb + (kt & 1) * HSTAGE + HA_SZ;
#pragma unroll
        for (int r = 0; r < 4; r++) {
            int hwl = warp * 16 + r * 4 + q;
            size_t pbase = ((size_t)b * Kv + kp) * HWv + n0 + hwl;
            int4   id4 = __ldg(pidx + pbase);
            float4 w4  = __ldg(pw + pbase);
            const float* base = xb + cg * 32 + cl * 4;
            float4 c00 = *(const float4*)(base + (size_t)id4.x * Cv);
            float4 c01 = *(const float4*)(base + (size_t)id4.y * Cv);
            float4 c10 = *(const float4*)(base + (size_t)id4.z * Cv);
            float4 c11 = *(const float4*)(base + (size_t)id4.w * Cv);
            float vx = w4.x * c00.x + w4.y * c01.x + w4.z * c10.x + w4.w * c11.x;
            float vy = w4.x * c00.y + w4.y * c01.y + w4.z * c10.y + w4.w * c11.y;
            float vz = w4.x * c00.z + w4.y * c01.z + w4.z * c10.z + w4.w * c11.z;
            float vw = w4.x * c00.w + w4.y * c01.w + w4.z * c10.w + w4.w * c11.w;
            __half2 h0 = __floats2half2_rn(vx, vy);
            __half2 h1 = __floats2half2_rn(vz, vw);
            uint2 u;
            u.x = *(unsigned int*)&h0;
            u.y = *(unsigned int*)&h1;
            *(uint2*)(Bs + hwl * AROWB + cl * 8) = u;   // cl*4 halfs = cl*8 bytes
        }
    };

    // race-free single-barrier pipeline (R14-validated schedule)
    issueA(0);
    buildB(0);
    asm volatile("cp.async.wait_group 0;\n" ::);
    __syncthreads();
    for (int kt = 0; kt < NT; kt++) {
        if (kt + 1 < NT) {
            issueA(kt + 1);
            buildB(kt + 1);
        }
        const char* As = smemb + (kt & 1) * HSTAGE;
        const char* Bs = As + HA_SZ;
#pragma unroll
        for (int s = 0; s < 2; s++) {          // two k16 steps cover TBK=32
            const int kb = s * 32;             // byte offset of k-group (16 halfs)
            unsigned int afr[4][4];
#pragma unroll
            for (int mi = 0; mi < 4; mi++) {
                int m = wm + mi * 16 + gid;
                afr[mi][0] = *(const unsigned int*)(As + m * AROWB + kb + tig * 4);
                afr[mi][1] = *(const unsigned int*)(As + (m + 8) * AROWB + kb + tig * 4);
                afr[mi][2] = *(const unsigned int*)(As + m * AROWB + kb + 16 + tig * 4);
                afr[mi][3] = *(const unsigned int*)(As + (m + 8) * AROWB + kb + 16 + tig * 4);
            }
            unsigned int bfr[4][2];
#pragma unroll
            for (int nj = 0; nj < 4; nj++) {
                int n = wn + nj * 8 + gid;
                bfr[nj][0] = *(const unsigned int*)(Bs + n * AROWB + kb + tig * 4);
                bfr[nj][1] = *(const unsigned int*)(Bs + n * AROWB + kb + 16 + tig * 4);
            }
#pragma unroll
            for (int mi = 0; mi < 4; mi++)
#pragma unroll
                for (int nj = 0; nj < 4; nj++)
                    mma_f16(acc[mi][nj], afr[mi], bfr[nj]);
        }
        if (kt + 1 < NT) asm volatile("cp.async.wait_group 0;\n" ::);
        __syncthreads();
    }

    // ---- epilogue: bias + BN + ReLU (direct stores; validated) ----
#pragma unroll
    for (int mi = 0; mi < 4; mi++) {
        int o0 = wm + mi * 16 + gid;
        int o1r = o0 + 8;
        float sc0 = bn_g[o0]  * rsqrtf(bn_v[o0]  + EPSv);
        float sc1 = bn_g[o1r] * rsqrtf(bn_v[o1r] + EPSv);
        float bb0 = bias[o0] - bn_m[o0], bb1 = bias[o1r] - bn_m[o1r];
        float bt0 = bn_b[o0], bt1 = bn_b[o1r];
#pragma unroll
        for (int nj = 0; nj < 4; nj++) {
            int ncol = n0 + wn + nj * 8 + 2 * tig;
            float v00 = fmaxf((acc[mi][nj][0] + bb0) * sc0 + bt0, 0.f);
            float v01 = fmaxf((acc[mi][nj][1] + bb0) * sc0 + bt0, 0.f);
            float v10 = fmaxf((acc[mi][nj][2] + bb1) * sc1 + bt1, 0.f);
            float v11 = fmaxf((acc[mi][nj][3] + bb1) * sc1 + bt1, 0.f);
            if (transposed) {
                float* ob = out + (size_t)b * HWv * Cv;
                ob[(size_t)(ncol)     * Cv + o0]  = v00;
                ob[(size_t)(ncol + 1) * Cv + o0]  = v01;
                ob[(size_t)(ncol)     * Cv + o1r] = v10;
                ob[(size_t)(ncol + 1) * Cv + o1r] = v11;
            } else {
                *(float2*)(out + ((size_t)b * Cv + o0)  * HWv + ncol) = make_float2(v00, v01);
                *(float2*)(out + ((size_t)b * Cv + o1r) * HWv + ncol) = make_float2(v10, v11);
            }
        }
    }
}

// ---------------- global max/mean pool per (b,c) ----------------
__global__ void pool_kernel(const float* __restrict__ x,
                            float* __restrict__ mx, float* __restrict__ av) {
    int bc = blockIdx.x;
    const float* p = x + (size_t)bc * HWv;
    float vmax = -3.4e38f, vsum = 0.f;
    for (int i = threadIdx.x; i < HWv; i += 256) {
        float t = p[i];
        vmax = fmaxf(vmax, t);
        vsum += t;
    }
    __shared__ float sm[256], ss[256];
    sm[threadIdx.x] = vmax; ss[threadIdx.x] = vsum;
    __syncthreads();
    for (int s = 128; s > 0; s >>= 1) {
        if (threadIdx.x < s) {
            sm[threadIdx.x] = fmaxf(sm[threadIdx.x], sm[threadIdx.x + s]);
            ss[threadIdx.x] += ss[threadIdx.x + s];
        }
        __syncthreads();
    }
    if (threadIdx.x == 0) { mx[bc] = sm[0]; av[bc] = ss[0] * (1.f / HWv); }
}

// ---------------- channel-attention MLP ----------------
__global__ void cam_kernel(const float* __restrict__ mx, const float* __restrict__ av,
                           const float* __restrict__ w1,
                           const float* __restrict__ w2,
                           float* __restrict__ ch) {
    int b = blockIdx.x;
    int tid = threadIdx.x;
    __shared__ float smx[128], sav[128], sh[32];
    smx[tid] = mx[b * 128 + tid];
    sav[tid] = av[b * 128 + tid];
    __syncthreads();
    if (tid < 32) {
        float a = 0.f, c = 0.f;
        for (int i = 0; i < 128; i++) {
            float wv = w1[tid * 128 + i];
            a = fmaf(smx[i], wv, a);
            c = fmaf(sav[i], wv, c);
        }
        sh[tid] = fmaxf(a, 0.f) + fmaxf(c, 0.f);
    }
    __syncthreads();
    float o = 0.f;
#pragma unroll
    for (int j = 0; j < 32; j++) o = fmaf(sh[j], w2[tid * 32 + j], o);
    ch[b * 128 + tid] = 1.f / (1.f + expf(-o));
}

// ---------------- in-place channel scale (float4) ----------------
__global__ void scale_kernel(float4* __restrict__ out, const float* __restrict__ ch) {
    size_t t = (size_t)blockIdx.x * blockDim.x + threadIdx.x;
    if (t >= (size_t)Bv * Cv * HWv / 4) return;
    float s = ch[t / (HWv / 4)];
    float4 v = out[t];
    v.x *= s; v.y *= s; v.z *= s; v.w *= s;
    out[t] = v;
}

// ---------------- launch ----------------
extern "C" void kernel_launch(void* const* d_in, const int* in_sizes, int n_in,
                              void* d_out, int out_size) {
    const float* x      = (const float*)d_in[0];
    const float* off_w1 = (const float*)d_in[1];
    const float* off_b1 = (const float*)d_in[2];
    const float* dcn_w1 = (const float*)d_in[3];
    const float* dcn_b1 = (const float*)d_in[4];
    const float* bn_g1  = (const float*)d_in[5];
    const float* bn_b1  = (const float*)d_in[6];
    const float* bn_m1  = (const float*)d_in[7];
    const float* bn_v1  = (const float*)d_in[8];
    const float* off_w2 = (const float*)d_in[9];
    const float* off_b2 = (const float*)d_in[10];
    const float* dcn_w2 = (const float*)d_in[11];
    const float* dcn_b2 = (const float*)d_in[12];
    const float* bn_g2  = (const float*)d_in[13];
    const float* bn_b2  = (const float*)d_in[14];
    const float* bn_m2  = (const float*)d_in[15];
    const float* bn_v2  = (const float*)d_in[16];
    const float* cam_w1 = (const float*)d_in[17];
    const float* cam_w2 = (const float*)d_in[18];
    float* out = (float*)d_out;

    float *xT, *o1T, *ow1, *ow2, *mxp, *avp, *chp;
    __half *wt1h, *wt2h;
    int4 *pidx; float4 *pw;
    cudaGetSymbolAddress((void**)&xT,   g_xT);
    cudaGetSymbolAddress((void**)&o1T,  g_o1T);
    cudaGetSymbolAddress((void**)&wt1h, g_wt1h);
    cudaGetSymbolAddress((void**)&wt2h, g_wt2h);
    cudaGetSymbolAddress((void**)&ow1,  g_ow1);
    cudaGetSymbolAddress((void**)&ow2,  g_ow2);
    cudaGetSymbolAddress((void**)&pidx, g_pidx);
    cudaGetSymbolAddress((void**)&pw,   g_pw);
    cudaGetSymbolAddress((void**)&mxp,  g_mx);
    cudaGetSymbolAddress((void**)&avp,  g_av);
    cudaGetSymbolAddress((void**)&chp,  g_ch);

    cudaFuncSetAttribute(fused_dcn_gemm_kernel,
                         cudaFuncAttributeMaxDynamicSharedMemorySize, FGEMM_SMEM);
    cudaFuncSetAttribute(off_gemm_prep_kernel,
                         cudaFuncAttributeMaxDynamicSharedMemorySize, OGEMM_SMEM);

    int  prepGrid = (Cv * KD + 255) / 256;
    dim3 trGrid(HWv / 32, Cv / 32, Bv);
    dim3 trBlk(32, 8);
    dim3 gemmGrid(HWv / TBN, Bv);
    int  scaleGrid = (Bv * Cv * HWv / 4 + 255) / 256;

    // weight prep (all layers, one launch)
    prep_weights_kernel<<<prepGrid, 256>>>(dcn_w1, dcn_w2, off_w1, off_w2,
                                           wt1h, wt2h, ow1, ow2);

    // layer 1 (writes o1T hw-major directly)
    transpose_kernel<<<trGrid, trBlk>>>(x, xT);
    off_gemm_prep_kernel<<<gemmGrid, 256, OGEMM_SMEM>>>(ow1, xT, off_b1, pidx, pw);
    fused_dcn_gemm_kernel<<<gemmGrid, 256, FGEMM_SMEM>>>(wt1h, xT, pidx, pw,
        dcn_b1, bn_g1, bn_b1, bn_m1, bn_v1, o1T, 1);

    // layer 2 (writes channel-major final)
    off_gemm_prep_kernel<<<gemmGrid, 256, OGEMM_SMEM>>>(ow2, o1T, off_b2, pidx, pw);
    fused_dcn_gemm_kernel<<<gemmGrid, 256, FGEMM_SMEM>>>(wt2h, o1T, pidx, pw,
        dcn_b2, bn_g2, bn_b2, bn_m2, bn_v2, out, 0);

    // channel attention
    pool_kernel<<<Bv * Cv, 256>>>(out, mxp, avp);
    cam_kernel<<<Bv, 128>>>(mxp, avp, cam_w1, cam_w2, chp);
    scale_kernel<<<scaleGrid, 256>>>((float4*)out, chp);
}